// round 2
// baseline (speedup 1.0000x reference)
#include <cuda_runtime.h>
#include <math.h>

#define NN 50000
#define EE 800000
#define KDIM 128     // IN_DIM
#define CD 128       // H*D output cols
#define NH 8
#define HD 16
#define APAD 132

// ---------------- device scratch ----------------
__device__ float g_Qh[(size_t)NN * CD];
__device__ float g_Kh[(size_t)NN * CD];
__device__ float g_Vh[(size_t)NN * CD];
__device__ float g_z[(size_t)NN * NH];

// ---------------- f32x2 packed helpers ----------------
__device__ __forceinline__ void ffma2(unsigned long long& d,
                                      unsigned long long a,
                                      unsigned long long b) {
    asm("fma.rn.f32x2 %0, %1, %2, %0;" : "+l"(d) : "l"(a), "l"(b));
}
__device__ __forceinline__ unsigned long long pack2(float x) {
    unsigned long long r; unsigned u = __float_as_uint(x);
    asm("mov.b64 %0, {%1, %1};" : "=l"(r) : "r"(u));
    return r;
}
__device__ __forceinline__ float2 unpack2(unsigned long long v) {
    unsigned lo, hi;
    asm("mov.b64 {%0, %1}, %2;" : "=r"(lo), "=r"(hi) : "l"(v));
    return make_float2(__uint_as_float(lo), __uint_as_float(hi));
}

// ---------------- merged node projection: Q,K,V = h@W + b ----------------
// 256 threads, BM=64 rows, thread tile 4x8, loops over 3 weight matrices.
__global__ __launch_bounds__(256, 2) void node_proj_qkv_kernel(
    const float* __restrict__ h,
    const float* __restrict__ Qw, const float* __restrict__ Qb,
    const float* __restrict__ Kw, const float* __restrict__ Kb,
    const float* __restrict__ Vw, const float* __restrict__ Vb,
    float* __restrict__ outQ, float* __restrict__ outK, float* __restrict__ outV)
{
    extern __shared__ float sm[];
    float* sW = sm;                 // 128*128
    float* sA = sm + KDIM * CD;     // 64*APAD

    const int tid = threadIdx.x;
    const int r0  = blockIdx.x * 64;

    // load A tile once (row guard)
    for (int i = tid; i < 64 * 32; i += 256) {
        int row = i >> 5, kc = i & 31;
        float4 v = make_float4(0.f, 0.f, 0.f, 0.f);
        int gr = r0 + row;
        if (gr < NN)
            v = reinterpret_cast<const float4*>(h + (size_t)gr * KDIM)[kc];
        *reinterpret_cast<float4*>(sA + row * APAD + kc * 4) = v;
    }

    const float* Ws[3] = {Qw, Kw, Vw};
    const float* Bs[3] = {Qb, Kb, Vb};
    float* Os[3] = {outQ, outK, outV};

    const int ty = tid >> 4, tx = tid & 15;
    const int c0 = tx * 8;
    const int ty4 = ty * 4;

    for (int m = 0; m < 3; ++m) {
        __syncthreads();
        const float* W = Ws[m];
        for (int i = tid; i < KDIM * CD / 4; i += 256)
            reinterpret_cast<float4*>(sW)[i] = reinterpret_cast<const float4*>(W)[i];
        __syncthreads();

        unsigned long long acc[4][4];
#pragma unroll
        for (int i = 0; i < 4; ++i)
#pragma unroll
            for (int p = 0; p < 4; ++p) acc[i][p] = 0ull;

#pragma unroll 2
        for (int kg = 0; kg < 32; ++kg) {
            float4 a4[4];
#pragma unroll
            for (int i = 0; i < 4; ++i)
                a4[i] = *reinterpret_cast<const float4*>(sA + (ty4 + i) * APAD + kg * 4);
#pragma unroll
            for (int kk = 0; kk < 4; ++kk) {
                const float* wp = sW + (kg * 4 + kk) * CD + c0;
                ulonglong2 w01 = *reinterpret_cast<const ulonglong2*>(wp);
                ulonglong2 w23 = *reinterpret_cast<const ulonglong2*>(wp + 4);
#pragma unroll
                for (int i = 0; i < 4; ++i) {
                    unsigned long long a2 = pack2(reinterpret_cast<const float*>(&a4[i])[kk]);
                    ffma2(acc[i][0], a2, w01.x);
                    ffma2(acc[i][1], a2, w01.y);
                    ffma2(acc[i][2], a2, w23.x);
                    ffma2(acc[i][3], a2, w23.y);
                }
            }
        }

        float bb[8];
        {
            float4 b0 = *reinterpret_cast<const float4*>(Bs[m] + c0);
            float4 b1 = *reinterpret_cast<const float4*>(Bs[m] + c0 + 4);
            bb[0]=b0.x; bb[1]=b0.y; bb[2]=b0.z; bb[3]=b0.w;
            bb[4]=b1.x; bb[5]=b1.y; bb[6]=b1.z; bb[7]=b1.w;
        }
        float* out = Os[m];
#pragma unroll
        for (int i = 0; i < 4; ++i) {
            int r = r0 + ty4 + i;
            if (r >= NN) continue;
            float o[8];
#pragma unroll
            for (int p = 0; p < 4; ++p) {
                float2 v = unpack2(acc[i][p]);
                o[2*p]   = v.x + bb[2*p];
                o[2*p+1] = v.y + bb[2*p+1];
            }
            reinterpret_cast<float4*>(out + (size_t)r * CD + c0)[0] =
                make_float4(o[0], o[1], o[2], o[3]);
            reinterpret_cast<float4*>(out + (size_t)r * CD + c0 + 4)[0] =
                make_float4(o[4], o[5], o[6], o[7]);
        }
    }
}

// ---------------- fused edge kernel ----------------
// 512 threads, 64 edges/block, thread tile 2 rows x 8 cols, dual GEMM (Ew, Rw)
// with f32x2 packed FMA; epilogue: score, e_out store, exp, atomic scatter.
__global__ __launch_bounds__(512, 1) void edge_kernel(
    const float* __restrict__ e,
    const float* __restrict__ kr,
    const int*  __restrict__ src,
    const int*  __restrict__ dst,
    const float* __restrict__ Ew, const float* __restrict__ Eb,
    const float* __restrict__ Rw, const float* __restrict__ Rb,
    float* __restrict__ out_h,
    float* __restrict__ out_e)
{
    extern __shared__ float sm[];
    float* sEw = sm;                          // 128*128
    float* sRw = sEw + KDIM * CD;             // 128*128
    float* sAe = sRw + KDIM * CD;             // 64*APAD
    float* sAk = sAe + 64 * APAD;             // 64*APAD
    int*   sidx = reinterpret_cast<int*>(sAk + 64 * APAD);  // 64 src + 64 dst

    const int tid = threadIdx.x;
    const int r0  = blockIdx.x * 64;

    // weights: 4096 float4 each, 512 threads -> 8 each
    for (int i = tid; i < KDIM * CD / 4; i += 512) {
        reinterpret_cast<float4*>(sEw)[i] = reinterpret_cast<const float4*>(Ew)[i];
        reinterpret_cast<float4*>(sRw)[i] = reinterpret_cast<const float4*>(Rw)[i];
    }
    // A tiles: 2048 float4 each
    for (int i = tid; i < 64 * 32; i += 512) {
        int row = i >> 5, kc = i & 31;
        float4 ve = reinterpret_cast<const float4*>(e  + (size_t)(r0 + row) * KDIM)[kc];
        float4 vk = reinterpret_cast<const float4*>(kr + (size_t)(r0 + row) * KDIM)[kc];
        *reinterpret_cast<float4*>(sAe + row * APAD + kc * 4) = ve;
        *reinterpret_cast<float4*>(sAk + row * APAD + kc * 4) = vk;
    }
    if (tid < 64) {
        sidx[tid]      = src[r0 + tid];
        sidx[64 + tid] = dst[r0 + tid];
    }
    __syncthreads();

    const int ty = tid >> 4, tx = tid & 15;   // ty 0..31, tx 0..15
    const int c0 = tx * 8;
    const int row0 = ty * 2;
    const int head = tx >> 1;

    unsigned long long accE[2][4], accR[2][4];
#pragma unroll
    for (int r = 0; r < 2; ++r)
#pragma unroll
        for (int p = 0; p < 4; ++p) { accE[r][p] = 0ull; accR[r][p] = 0ull; }

#pragma unroll 2
    for (int kg = 0; kg < 32; ++kg) {
        float4 a4[2], b4[2];
#pragma unroll
        for (int r = 0; r < 2; ++r) {
            a4[r] = *reinterpret_cast<const float4*>(sAe + (row0 + r) * APAD + kg * 4);
            b4[r] = *reinterpret_cast<const float4*>(sAk + (row0 + r) * APAD + kg * 4);
        }
#pragma unroll
        for (int kk = 0; kk < 4; ++kk) {
            const int k = kg * 4 + kk;
            const float* wp = sEw + k * CD + c0;
            const float* up = sRw + k * CD + c0;
            ulonglong2 e01 = *reinterpret_cast<const ulonglong2*>(wp);
            ulonglong2 e23 = *reinterpret_cast<const ulonglong2*>(wp + 4);
            ulonglong2 u01 = *reinterpret_cast<const ulonglong2*>(up);
            ulonglong2 u23 = *reinterpret_cast<const ulonglong2*>(up + 4);
#pragma unroll
            for (int r = 0; r < 2; ++r) {
                unsigned long long a2 = pack2(reinterpret_cast<const float*>(&a4[r])[kk]);
                ffma2(accE[r][0], a2, e01.x);
                ffma2(accE[r][1], a2, e01.y);
                ffma2(accE[r][2], a2, e23.x);
                ffma2(accE[r][3], a2, e23.y);
                unsigned long long b2 = pack2(reinterpret_cast<const float*>(&b4[r])[kk]);
                ffma2(accR[r][0], b2, u01.x);
                ffma2(accR[r][1], b2, u01.y);
                ffma2(accR[r][2], b2, u23.x);
                ffma2(accR[r][3], b2, u23.y);
            }
        }
    }

    float eb[8], rb[8];
    {
        float4 b0 = *reinterpret_cast<const float4*>(Eb + c0);
        float4 b1 = *reinterpret_cast<const float4*>(Eb + c0 + 4);
        eb[0]=b0.x; eb[1]=b0.y; eb[2]=b0.z; eb[3]=b0.w;
        eb[4]=b1.x; eb[5]=b1.y; eb[6]=b1.z; eb[7]=b1.w;
        float4 c0v = *reinterpret_cast<const float4*>(Rb + c0);
        float4 c1v = *reinterpret_cast<const float4*>(Rb + c0 + 4);
        rb[0]=c0v.x; rb[1]=c0v.y; rb[2]=c0v.z; rb[3]=c0v.w;
        rb[4]=c1v.x; rb[5]=c1v.y; rb[6]=c1v.z; rb[7]=c1v.w;
    }

#pragma unroll
    for (int r = 0; r < 2; ++r) {
        const int row = row0 + r;
        const int redge = r0 + row;
        const int sn = sidx[row];
        const int dn = sidx[64 + row];

        const float4* Kp = reinterpret_cast<const float4*>(g_Kh + (size_t)sn * CD + c0);
        const float4* Qp = reinterpret_cast<const float4*>(g_Qh + (size_t)dn * CD + c0);
        const float4* Vp = reinterpret_cast<const float4*>(g_Vh + (size_t)sn * CD + c0);
        float4 K0 = Kp[0], K1 = Kp[1];
        float4 Q0 = Qp[0], Q1 = Qp[1];
        float4 V0 = Vp[0], V1 = Vp[1];

        float kk8[8] = {K0.x, K0.y, K0.z, K0.w, K1.x, K1.y, K1.z, K1.w};
        float qq8[8] = {Q0.x, Q0.y, Q0.z, Q0.w, Q1.x, Q1.y, Q1.z, Q1.w};
        float vv8[8] = {V0.x, V0.y, V0.z, V0.w, V1.x, V1.y, V1.z, V1.w};

        float pe[8], pr[8];
#pragma unroll
        for (int p = 0; p < 4; ++p) {
            float2 ve2 = unpack2(accE[r][p]);
            float2 vr2 = unpack2(accR[r][p]);
            pe[2*p]   = ve2.x + eb[2*p];
            pe[2*p+1] = ve2.y + eb[2*p+1];
            pr[2*p]   = vr2.x + rb[2*p];
            pr[2*p+1] = vr2.y + rb[2*p+1];
        }

        float sc[8];
        float part = 0.f;
#pragma unroll
        for (int j = 0; j < 8; ++j) {
            float t = fmaf(kk8[j] * qq8[j], 0.25f, pr[j]);
            t = t * pe[j];
            sc[j] = t;
            part += t;
        }

        reinterpret_cast<float4*>(out_e + (size_t)redge * CD + c0)[0] =
            make_float4(sc[0], sc[1], sc[2], sc[3]);
        reinterpret_cast<float4*>(out_e + (size_t)redge * CD + c0 + 4)[0] =
            make_float4(sc[4], sc[5], sc[6], sc[7]);

        float tot = part + __shfl_xor_sync(0xffffffffu, part, 1);
        tot = fminf(fmaxf(tot, -5.0f), 5.0f);
        float sval = __expf(tot);

        float* w = out_h + (size_t)dn * CD + c0;
#pragma unroll
        for (int j = 0; j < 8; ++j) atomicAdd(w + j, vv8[j] * sval);
        if ((tx & 1) == 0) atomicAdd(&g_z[(size_t)dn * NH + head], sval);
    }
}

// ---------------- finalize: h_out = wV / (z + 1e-6) ----------------
__global__ __launch_bounds__(256) void finalize_kernel(float* __restrict__ out_h)
{
    int i = blockIdx.x * 256 + threadIdx.x;        // float4 index
    const int total = NN * CD / 4;
    if (i >= total) return;
    int n  = i >> 5;
    int cg = i & 31;
    int head = cg >> 2;
    float z = g_z[(size_t)n * NH + head] + 1e-6f;
    float inv = 1.0f / z;
    float4 v = reinterpret_cast<float4*>(out_h)[i];
    v.x *= inv; v.y *= inv; v.z *= inv; v.w *= inv;
    reinterpret_cast<float4*>(out_h)[i] = v;
}

// ---------------- launch ----------------
extern "C" void kernel_launch(void* const* d_in, const int* in_sizes, int n_in,
                              void* d_out, int out_size)
{
    const float* h   = (const float*)d_in[0];
    const float* e   = (const float*)d_in[1];
    const float* kr  = (const float*)d_in[2];
    const int*   src = (const int*)  d_in[3];
    const int*   dst = (const int*)  d_in[4];
    const float* Qw  = (const float*)d_in[5];
    const float* Qb  = (const float*)d_in[6];
    const float* Kw  = (const float*)d_in[7];
    const float* Kb  = (const float*)d_in[8];
    const float* Vw  = (const float*)d_in[9];
    const float* Vb  = (const float*)d_in[10];
    const float* Ew  = (const float*)d_in[11];
    const float* Eb  = (const float*)d_in[12];
    const float* Rw  = (const float*)d_in[13];
    const float* Rb  = (const float*)d_in[14];

    float* out_h = (float*)d_out;
    float* out_e = (float*)d_out + (size_t)NN * CD;

    const size_t NODE_SMEM = (size_t)(KDIM * CD + 64 * APAD) * 4;
    const size_t EDGE_SMEM = (size_t)(2 * KDIM * CD + 2 * 64 * APAD) * 4 + 128 * 4;

    cudaFuncSetAttribute(node_proj_qkv_kernel, cudaFuncAttributeMaxDynamicSharedMemorySize, (int)NODE_SMEM);
    cudaFuncSetAttribute(edge_kernel,          cudaFuncAttributeMaxDynamicSharedMemorySize, (int)EDGE_SMEM);

    cudaMemsetAsync(out_h, 0, (size_t)NN * CD * sizeof(float));
    void* zp = nullptr;
    cudaGetSymbolAddress(&zp, g_z);
    cudaMemsetAsync(zp, 0, (size_t)NN * NH * sizeof(float));

    void *qp, *kp, *vp;
    cudaGetSymbolAddress(&qp, g_Qh);
    cudaGetSymbolAddress(&kp, g_Kh);
    cudaGetSymbolAddress(&vp, g_Vh);

    const int nodeBlocks = (NN + 63) / 64;  // 782
    node_proj_qkv_kernel<<<nodeBlocks, 256, NODE_SMEM>>>(
        h, Qw, Qb, Kw, Kb, Vw, Vb, (float*)qp, (float*)kp, (float*)vp);

    const int edgeBlocks = EE / 64;         // 12500
    edge_kernel<<<edgeBlocks, 512, EDGE_SMEM>>>(e, kr, src, dst, Ew, Eb, Rw, Rb, out_h, out_e);

    const int finBlocks = (NN * CD / 4 + 255) / 256;
    finalize_kernel<<<finBlocks, 256>>>(out_h);
}

// round 3
// speedup vs baseline: 1.6582x; 1.6582x over previous
#include <cuda_runtime.h>
#include <math.h>

#define NN 50000
#define EE 800000
#define KDIM 128     // IN_DIM
#define CD 128       // H*D output cols
#define NH 8
#define HD 16
#define APAD 132

#define BM 128       // edges per block (edge kernel)
#define BN 64        // cols per block (4 heads)
#define CHK 32       // K chunk
#define ASTR 33      // A smem row stride (conflict-free scalar reads)

// ---------------- device scratch ----------------
__device__ float g_Qh[(size_t)NN * CD];
__device__ float g_Kh[(size_t)NN * CD];
__device__ float g_Vh[(size_t)NN * CD];
__device__ float g_z[(size_t)NN * NH];

// ---------------- merged node projection: Q,K,V = h@W + b ----------------
__global__ __launch_bounds__(256, 2) void node_proj_qkv_kernel(
    const float* __restrict__ h,
    const float* __restrict__ Qw, const float* __restrict__ Qb,
    const float* __restrict__ Kw, const float* __restrict__ Kb,
    const float* __restrict__ Vw, const float* __restrict__ Vb,
    float* __restrict__ outQ, float* __restrict__ outK, float* __restrict__ outV)
{
    extern __shared__ float sm[];
    float* sW = sm;                 // 128*128
    float* sA = sm + KDIM * CD;     // 64*APAD

    const int tid = threadIdx.x;
    const int r0  = blockIdx.x * 64;

    for (int i = tid; i < 64 * 32; i += 256) {
        int row = i >> 5, kc = i & 31;
        float4 v = make_float4(0.f, 0.f, 0.f, 0.f);
        int gr = r0 + row;
        if (gr < NN)
            v = reinterpret_cast<const float4*>(h + (size_t)gr * KDIM)[kc];
        *reinterpret_cast<float4*>(sA + row * APAD + kc * 4) = v;
    }

    const float* Ws[3] = {Qw, Kw, Vw};
    const float* Bs[3] = {Qb, Kb, Vb};
    float* Os[3] = {outQ, outK, outV};

    const int ty = tid >> 4, tx = tid & 15;
    const int c0 = tx * 8;
    const int ty4 = ty * 4;

    for (int m = 0; m < 3; ++m) {
        __syncthreads();
        const float* W = Ws[m];
        for (int i = tid; i < KDIM * CD / 4; i += 256)
            reinterpret_cast<float4*>(sW)[i] = reinterpret_cast<const float4*>(W)[i];
        __syncthreads();

        float acc[4][8];
#pragma unroll
        for (int i = 0; i < 4; ++i)
#pragma unroll
            for (int j = 0; j < 8; ++j) acc[i][j] = 0.f;

#pragma unroll 4
        for (int k = 0; k < KDIM; ++k) {
            float4 w0 = *reinterpret_cast<const float4*>(sW + k * CD + c0);
            float4 w1 = *reinterpret_cast<const float4*>(sW + k * CD + c0 + 4);
            float we[8] = {w0.x, w0.y, w0.z, w0.w, w1.x, w1.y, w1.z, w1.w};
#pragma unroll
            for (int i = 0; i < 4; ++i) {
                float a = sA[(ty4 + i) * APAD + k];
#pragma unroll
                for (int j = 0; j < 8; ++j) acc[i][j] = fmaf(a, we[j], acc[i][j]);
            }
        }

        float bb[8];
        {
            float4 b0 = *reinterpret_cast<const float4*>(Bs[m] + c0);
            float4 b1 = *reinterpret_cast<const float4*>(Bs[m] + c0 + 4);
            bb[0]=b0.x; bb[1]=b0.y; bb[2]=b0.z; bb[3]=b0.w;
            bb[4]=b1.x; bb[5]=b1.y; bb[6]=b1.z; bb[7]=b1.w;
        }
        float* out = Os[m];
#pragma unroll
        for (int i = 0; i < 4; ++i) {
            int r = r0 + ty4 + i;
            if (r >= NN) continue;
            reinterpret_cast<float4*>(out + (size_t)r * CD + c0)[0] =
                make_float4(acc[i][0]+bb[0], acc[i][1]+bb[1], acc[i][2]+bb[2], acc[i][3]+bb[3]);
            reinterpret_cast<float4*>(out + (size_t)r * CD + c0 + 4)[0] =
                make_float4(acc[i][4]+bb[4], acc[i][5]+bb[5], acc[i][6]+bb[6], acc[i][7]+bb[7]);
        }
    }
}

// ---------------- fused edge kernel (head-split) ----------------
// Block: 128 edges x 64 cols (4 heads). 256 threads, 2 CTAs/SM.
// Dual GEMM (Ew,Rw half-width in smem), A chunked in K (4x32, stride-33 smem).
// Epilogue: score, e_out store, per-head exp, atomic scatter wV + z.
__global__ __launch_bounds__(256, 2) void edge_kernel(
    const float* __restrict__ e,
    const float* __restrict__ kr,
    const int*  __restrict__ src,
    const int*  __restrict__ dst,
    const float* __restrict__ Ew, const float* __restrict__ Eb,
    const float* __restrict__ Rw, const float* __restrict__ Rb,
    float* __restrict__ out_h,
    float* __restrict__ out_e)
{
    extern __shared__ float sm[];
    float* sEw = sm;                           // 128*64
    float* sRw = sEw + KDIM * BN;              // 128*64
    float* sAe = sRw + KDIM * BN;              // 128*ASTR
    float* sAk = sAe + BM * ASTR;              // 128*ASTR
    int*   sidx = reinterpret_cast<int*>(sAk + BM * ASTR);  // 128 src + 128 dst

    const int tid = threadIdx.x;
    const int r0    = blockIdx.x * BM;
    const int cbase = blockIdx.y * BN;

    // weights (half width): 128 rows x 16 float4 per matrix
    for (int i = tid; i < KDIM * (BN / 4); i += 256) {
        int k = i >> 4, q = i & 15;
        reinterpret_cast<float4*>(sEw + k * BN)[q] =
            *reinterpret_cast<const float4*>(Ew + (size_t)k * CD + cbase + q * 4);
        reinterpret_cast<float4*>(sRw + k * BN)[q] =
            *reinterpret_cast<const float4*>(Rw + (size_t)k * CD + cbase + q * 4);
    }
    if (tid < BM) {
        sidx[tid]       = src[r0 + tid];
        sidx[BM + tid]  = dst[r0 + tid];
    }

    const int tx = tid & 7;        // col group (8 cols)
    const int ty = tid >> 3;       // row group (4 rows), 0..31
    const int c0 = tx * 8;
    const int ty4 = ty * 4;

    float accE[4][8], accR[4][8];
#pragma unroll
    for (int i = 0; i < 4; ++i)
#pragma unroll
        for (int j = 0; j < 8; ++j) { accE[i][j] = 0.f; accR[i][j] = 0.f; }

    for (int ch = 0; ch < KDIM / CHK; ++ch) {
        __syncthreads();
        // fill A chunk: 128 rows x 8 float4 per matrix, scalar STS (stride 33)
        for (int i = tid; i < BM * (CHK / 4); i += 256) {
            int row = i >> 3, q = i & 7;
            const float* ge = e  + (size_t)(r0 + row) * KDIM + ch * CHK + q * 4;
            const float* gk = kr + (size_t)(r0 + row) * KDIM + ch * CHK + q * 4;
            float4 ve = *reinterpret_cast<const float4*>(ge);
            float4 vk = *reinterpret_cast<const float4*>(gk);
            float* pe = sAe + row * ASTR + q * 4;
            float* pk = sAk + row * ASTR + q * 4;
            pe[0]=ve.x; pe[1]=ve.y; pe[2]=ve.z; pe[3]=ve.w;
            pk[0]=vk.x; pk[1]=vk.y; pk[2]=vk.z; pk[3]=vk.w;
        }
        __syncthreads();

#pragma unroll 4
        for (int kk = 0; kk < CHK; ++kk) {
            const int k = ch * CHK + kk;
            float4 e0 = *reinterpret_cast<const float4*>(sEw + k * BN + c0);
            float4 e1 = *reinterpret_cast<const float4*>(sEw + k * BN + c0 + 4);
            float4 u0 = *reinterpret_cast<const float4*>(sRw + k * BN + c0);
            float4 u1 = *reinterpret_cast<const float4*>(sRw + k * BN + c0 + 4);
            float we[8] = {e0.x, e0.y, e0.z, e0.w, e1.x, e1.y, e1.z, e1.w};
            float wr[8] = {u0.x, u0.y, u0.z, u0.w, u1.x, u1.y, u1.z, u1.w};
#pragma unroll
            for (int i = 0; i < 4; ++i) {
                float a = sAe[(ty4 + i) * ASTR + kk];
                float b = sAk[(ty4 + i) * ASTR + kk];
#pragma unroll
                for (int j = 0; j < 8; ++j) {
                    accE[i][j] = fmaf(a, we[j], accE[i][j]);
                    accR[i][j] = fmaf(b, wr[j], accR[i][j]);
                }
            }
        }
    }

    // biases for this col slice
    float eb[8], rb[8];
    {
        float4 b0 = *reinterpret_cast<const float4*>(Eb + cbase + c0);
        float4 b1 = *reinterpret_cast<const float4*>(Eb + cbase + c0 + 4);
        eb[0]=b0.x; eb[1]=b0.y; eb[2]=b0.z; eb[3]=b0.w;
        eb[4]=b1.x; eb[5]=b1.y; eb[6]=b1.z; eb[7]=b1.w;
        float4 c0v = *reinterpret_cast<const float4*>(Rb + cbase + c0);
        float4 c1v = *reinterpret_cast<const float4*>(Rb + cbase + c0 + 4);
        rb[0]=c0v.x; rb[1]=c0v.y; rb[2]=c0v.z; rb[3]=c0v.w;
        rb[4]=c1v.x; rb[5]=c1v.y; rb[6]=c1v.z; rb[7]=c1v.w;
    }

    const int head = blockIdx.y * 4 + (tx >> 1);

#pragma unroll
    for (int i = 0; i < 4; ++i) {
        const int row   = ty4 + i;
        const int redge = r0 + row;
        const int sn = sidx[row];
        const int dn = sidx[BM + row];

        const float4* Kp = reinterpret_cast<const float4*>(g_Kh + (size_t)sn * CD + cbase + c0);
        const float4* Qp = reinterpret_cast<const float4*>(g_Qh + (size_t)dn * CD + cbase + c0);
        const float4* Vp = reinterpret_cast<const float4*>(g_Vh + (size_t)sn * CD + cbase + c0);
        float4 K0 = Kp[0], K1 = Kp[1];
        float4 Q0 = Qp[0], Q1 = Qp[1];
        float4 V0 = Vp[0], V1 = Vp[1];

        float kk8[8] = {K0.x, K0.y, K0.z, K0.w, K1.x, K1.y, K1.z, K1.w};
        float qq8[8] = {Q0.x, Q0.y, Q0.z, Q0.w, Q1.x, Q1.y, Q1.z, Q1.w};
        float vv8[8] = {V0.x, V0.y, V0.z, V0.w, V1.x, V1.y, V1.z, V1.w};

        float sc[8];
        float part = 0.f;
#pragma unroll
        for (int j = 0; j < 8; ++j) {
            float t = fmaf(kk8[j] * qq8[j], 0.25f, accR[i][j] + rb[j]);
            t = t * (accE[i][j] + eb[j]);
            sc[j] = t;
            part += t;
        }

        reinterpret_cast<float4*>(out_e + (size_t)redge * CD + cbase + c0)[0] =
            make_float4(sc[0], sc[1], sc[2], sc[3]);
        reinterpret_cast<float4*>(out_e + (size_t)redge * CD + cbase + c0 + 4)[0] =
            make_float4(sc[4], sc[5], sc[6], sc[7]);

        float tot = part + __shfl_xor_sync(0xffffffffu, part, 1);
        tot = fminf(fmaxf(tot, -5.0f), 5.0f);
        float sval = __expf(tot);

        float* w = out_h + (size_t)dn * CD + cbase + c0;
#pragma unroll
        for (int j = 0; j < 8; ++j) atomicAdd(w + j, vv8[j] * sval);
        if ((tx & 1) == 0) atomicAdd(&g_z[(size_t)dn * NH + head], sval);
    }
}

// ---------------- finalize: h_out = wV / (z + 1e-6) ----------------
__global__ __launch_bounds__(256) void finalize_kernel(float* __restrict__ out_h)
{
    int i = blockIdx.x * 256 + threadIdx.x;        // float4 index
    const int total = NN * CD / 4;
    if (i >= total) return;
    int n  = i >> 5;
    int cg = i & 31;
    int head = cg >> 2;
    float z = g_z[(size_t)n * NH + head] + 1e-6f;
    float inv = 1.0f / z;
    float4 v = reinterpret_cast<float4*>(out_h)[i];
    v.x *= inv; v.y *= inv; v.z *= inv; v.w *= inv;
    reinterpret_cast<float4*>(out_h)[i] = v;
}

// ---------------- launch ----------------
extern "C" void kernel_launch(void* const* d_in, const int* in_sizes, int n_in,
                              void* d_out, int out_size)
{
    const float* h   = (const float*)d_in[0];
    const float* e   = (const float*)d_in[1];
    const float* kr  = (const float*)d_in[2];
    const int*   src = (const int*)  d_in[3];
    const int*   dst = (const int*)  d_in[4];
    const float* Qw  = (const float*)d_in[5];
    const float* Qb  = (const float*)d_in[6];
    const float* Kw  = (const float*)d_in[7];
    const float* Kb  = (const float*)d_in[8];
    const float* Vw  = (const float*)d_in[9];
    const float* Vb  = (const float*)d_in[10];
    const float* Ew  = (const float*)d_in[11];
    const float* Eb  = (const float*)d_in[12];
    const float* Rw  = (const float*)d_in[13];
    const float* Rb  = (const float*)d_in[14];

    float* out_h = (float*)d_out;
    float* out_e = (float*)d_out + (size_t)NN * CD;

    const size_t NODE_SMEM = (size_t)(KDIM * CD + 64 * APAD) * 4;                   // ~99 KB
    const size_t EDGE_SMEM = (size_t)(2 * KDIM * BN + 2 * BM * ASTR) * 4 + 256 * 4; // ~98 KB

    cudaFuncSetAttribute(node_proj_qkv_kernel, cudaFuncAttributeMaxDynamicSharedMemorySize, (int)NODE_SMEM);
    cudaFuncSetAttribute(edge_kernel,          cudaFuncAttributeMaxDynamicSharedMemorySize, (int)EDGE_SMEM);

    cudaMemsetAsync(out_h, 0, (size_t)NN * CD * sizeof(float));
    void* zp = nullptr;
    cudaGetSymbolAddress(&zp, g_z);
    cudaMemsetAsync(zp, 0, (size_t)NN * NH * sizeof(float));

    void *qp, *kp, *vp;
    cudaGetSymbolAddress(&qp, g_Qh);
    cudaGetSymbolAddress(&kp, g_Kh);
    cudaGetSymbolAddress(&vp, g_Vh);

    const int nodeBlocks = (NN + 63) / 64;  // 782
    node_proj_qkv_kernel<<<nodeBlocks, 256, NODE_SMEM>>>(
        h, Qw, Qb, Kw, Kb, Vw, Vb, (float*)qp, (float*)kp, (float*)vp);

    dim3 eg(EE / BM, 2);                    // 6250 x 2
    edge_kernel<<<eg, 256, EDGE_SMEM>>>(e, kr, src, dst, Ew, Eb, Rw, Rb, out_h, out_e);

    const int finBlocks = (NN * CD / 4 + 255) / 256;
    finalize_kernel<<<finBlocks, 256>>>(out_h);
}

// round 4
// speedup vs baseline: 1.7750x; 1.0704x over previous
#include <cuda_runtime.h>
#include <math.h>

#define NN 50000
#define EE 800000
#define KDIM 128     // IN_DIM
#define CD 128       // H*D output cols
#define NH 8
#define HD 16
#define APAD 132

#define BM 128       // edges per block (edge kernel)
#define BN 64        // cols per block (4 heads)
#define CHK 32       // K chunk
#define ASTR 36      // A smem row stride (float4-aligned, conflict-staggered)

// ---------------- device scratch ----------------
__device__ float g_Qh[(size_t)NN * CD];
__device__ float g_Kh[(size_t)NN * CD];
__device__ float g_Vh[(size_t)NN * CD];
__device__ float g_z[(size_t)NN * NH];

__device__ __forceinline__ void red_add_v4(float* p, float a, float b, float c, float d) {
    asm volatile("red.global.add.v4.f32 [%0], {%1, %2, %3, %4};"
                 :: "l"(p), "f"(a), "f"(b), "f"(c), "f"(d) : "memory");
}

// ---------------- merged node projection: Q,K,V = h@W + b ----------------
__global__ __launch_bounds__(256, 2) void node_proj_qkv_kernel(
    const float* __restrict__ h,
    const float* __restrict__ Qw, const float* __restrict__ Qb,
    const float* __restrict__ Kw, const float* __restrict__ Kb,
    const float* __restrict__ Vw, const float* __restrict__ Vb,
    float* __restrict__ outQ, float* __restrict__ outK, float* __restrict__ outV)
{
    extern __shared__ float sm[];
    float* sW = sm;                 // 128*128
    float* sA = sm + KDIM * CD;     // 64*APAD

    const int tid = threadIdx.x;
    const int r0  = blockIdx.x * 64;

    for (int i = tid; i < 64 * 32; i += 256) {
        int row = i >> 5, kc = i & 31;
        float4 v = make_float4(0.f, 0.f, 0.f, 0.f);
        int gr = r0 + row;
        if (gr < NN)
            v = reinterpret_cast<const float4*>(h + (size_t)gr * KDIM)[kc];
        *reinterpret_cast<float4*>(sA + row * APAD + kc * 4) = v;
    }

    const float* Ws[3] = {Qw, Kw, Vw};
    const float* Bs[3] = {Qb, Kb, Vb};
    float* Os[3] = {outQ, outK, outV};

    const int ty = tid >> 4, tx = tid & 15;
    const int c0 = tx * 8;
    const int ty4 = ty * 4;

    for (int m = 0; m < 3; ++m) {
        __syncthreads();
        const float* W = Ws[m];
        for (int i = tid; i < KDIM * CD / 4; i += 256)
            reinterpret_cast<float4*>(sW)[i] = reinterpret_cast<const float4*>(W)[i];
        __syncthreads();

        float acc[4][8];
#pragma unroll
        for (int i = 0; i < 4; ++i)
#pragma unroll
            for (int j = 0; j < 8; ++j) acc[i][j] = 0.f;

#pragma unroll
        for (int kg = 0; kg < KDIM / 4; ++kg) {
            float4 a4[4];
#pragma unroll
            for (int i = 0; i < 4; ++i)
                a4[i] = *reinterpret_cast<const float4*>(sA + (ty4 + i) * APAD + kg * 4);
#pragma unroll
            for (int kk = 0; kk < 4; ++kk) {
                const int k = kg * 4 + kk;
                float4 w0 = *reinterpret_cast<const float4*>(sW + k * CD + c0);
                float4 w1 = *reinterpret_cast<const float4*>(sW + k * CD + c0 + 4);
                float we[8] = {w0.x, w0.y, w0.z, w0.w, w1.x, w1.y, w1.z, w1.w};
#pragma unroll
                for (int i = 0; i < 4; ++i) {
                    float a = reinterpret_cast<const float*>(&a4[i])[kk];
#pragma unroll
                    for (int j = 0; j < 8; ++j) acc[i][j] = fmaf(a, we[j], acc[i][j]);
                }
            }
        }

        float bb[8];
        {
            float4 b0 = *reinterpret_cast<const float4*>(Bs[m] + c0);
            float4 b1 = *reinterpret_cast<const float4*>(Bs[m] + c0 + 4);
            bb[0]=b0.x; bb[1]=b0.y; bb[2]=b0.z; bb[3]=b0.w;
            bb[4]=b1.x; bb[5]=b1.y; bb[6]=b1.z; bb[7]=b1.w;
        }
        float* out = Os[m];
#pragma unroll
        for (int i = 0; i < 4; ++i) {
            int r = r0 + ty4 + i;
            if (r >= NN) continue;
            reinterpret_cast<float4*>(out + (size_t)r * CD + c0)[0] =
                make_float4(acc[i][0]+bb[0], acc[i][1]+bb[1], acc[i][2]+bb[2], acc[i][3]+bb[3]);
            reinterpret_cast<float4*>(out + (size_t)r * CD + c0 + 4)[0] =
                make_float4(acc[i][4]+bb[4], acc[i][5]+bb[5], acc[i][6]+bb[6], acc[i][7]+bb[7]);
        }
    }
}

// ---------------- fused edge kernel (head-split) ----------------
__global__ __launch_bounds__(256, 2) void edge_kernel(
    const float* __restrict__ e,
    const float* __restrict__ kr,
    const int*  __restrict__ src,
    const int*  __restrict__ dst,
    const float* __restrict__ Ew, const float* __restrict__ Eb,
    const float* __restrict__ Rw, const float* __restrict__ Rb,
    float* __restrict__ out_h,
    float* __restrict__ out_e)
{
    extern __shared__ float sm[];
    float* sEw = sm;                           // 128*64
    float* sRw = sEw + KDIM * BN;              // 128*64
    float* sAe = sRw + KDIM * BN;              // 128*ASTR
    float* sAk = sAe + BM * ASTR;              // 128*ASTR
    int*   sidx = reinterpret_cast<int*>(sAk + BM * ASTR);  // 128 src + 128 dst

    const int tid = threadIdx.x;
    const int r0    = blockIdx.x * BM;
    const int cbase = blockIdx.y * BN;

    // weights (half width): 128 rows x 16 float4 per matrix
    for (int i = tid; i < KDIM * (BN / 4); i += 256) {
        int k = i >> 4, q = i & 15;
        reinterpret_cast<float4*>(sEw + k * BN)[q] =
            *reinterpret_cast<const float4*>(Ew + (size_t)k * CD + cbase + q * 4);
        reinterpret_cast<float4*>(sRw + k * BN)[q] =
            *reinterpret_cast<const float4*>(Rw + (size_t)k * CD + cbase + q * 4);
    }
    if (tid < BM) {
        sidx[tid]       = src[r0 + tid];
        sidx[BM + tid]  = dst[r0 + tid];
    }

    const int tx = tid & 7;        // col group (8 cols)
    const int ty = tid >> 3;       // row group (4 rows), 0..31
    const int c0 = tx * 8;
    const int ty4 = ty * 4;

    float accE[4][8], accR[4][8];
#pragma unroll
    for (int i = 0; i < 4; ++i)
#pragma unroll
        for (int j = 0; j < 8; ++j) { accE[i][j] = 0.f; accR[i][j] = 0.f; }

    for (int ch = 0; ch < KDIM / CHK; ++ch) {
        __syncthreads();
        // fill A chunk: 128 rows x 8 float4 per matrix (stride-36 rows)
        for (int i = tid; i < BM * (CHK / 4); i += 256) {
            int row = i >> 3, q = i & 7;
            float4 ve = *reinterpret_cast<const float4*>(e  + (size_t)(r0 + row) * KDIM + ch * CHK + q * 4);
            float4 vk = *reinterpret_cast<const float4*>(kr + (size_t)(r0 + row) * KDIM + ch * CHK + q * 4);
            *reinterpret_cast<float4*>(sAe + row * ASTR + q * 4) = ve;
            *reinterpret_cast<float4*>(sAk + row * ASTR + q * 4) = vk;
        }
        __syncthreads();

#pragma unroll
        for (int kg = 0; kg < CHK / 4; ++kg) {
            float4 ae[4], ak[4];
#pragma unroll
            for (int i = 0; i < 4; ++i) {
                ae[i] = *reinterpret_cast<const float4*>(sAe + (ty4 + i) * ASTR + kg * 4);
                ak[i] = *reinterpret_cast<const float4*>(sAk + (ty4 + i) * ASTR + kg * 4);
            }
#pragma unroll
            for (int kk = 0; kk < 4; ++kk) {
                const int k = ch * CHK + kg * 4 + kk;
                float4 e0 = *reinterpret_cast<const float4*>(sEw + k * BN + c0);
                float4 e1 = *reinterpret_cast<const float4*>(sEw + k * BN + c0 + 4);
                float4 u0 = *reinterpret_cast<const float4*>(sRw + k * BN + c0);
                float4 u1 = *reinterpret_cast<const float4*>(sRw + k * BN + c0 + 4);
                float we[8] = {e0.x, e0.y, e0.z, e0.w, e1.x, e1.y, e1.z, e1.w};
                float wr[8] = {u0.x, u0.y, u0.z, u0.w, u1.x, u1.y, u1.z, u1.w};
#pragma unroll
                for (int i = 0; i < 4; ++i) {
                    float a = reinterpret_cast<const float*>(&ae[i])[kk];
                    float b = reinterpret_cast<const float*>(&ak[i])[kk];
#pragma unroll
                    for (int j = 0; j < 8; ++j) {
                        accE[i][j] = fmaf(a, we[j], accE[i][j]);
                        accR[i][j] = fmaf(b, wr[j], accR[i][j]);
                    }
                }
            }
        }
    }

    // biases for this col slice
    float eb[8], rb[8];
    {
        float4 b0 = *reinterpret_cast<const float4*>(Eb + cbase + c0);
        float4 b1 = *reinterpret_cast<const float4*>(Eb + cbase + c0 + 4);
        eb[0]=b0.x; eb[1]=b0.y; eb[2]=b0.z; eb[3]=b0.w;
        eb[4]=b1.x; eb[5]=b1.y; eb[6]=b1.z; eb[7]=b1.w;
        float4 c0v = *reinterpret_cast<const float4*>(Rb + cbase + c0);
        float4 c1v = *reinterpret_cast<const float4*>(Rb + cbase + c0 + 4);
        rb[0]=c0v.x; rb[1]=c0v.y; rb[2]=c0v.z; rb[3]=c0v.w;
        rb[4]=c1v.x; rb[5]=c1v.y; rb[6]=c1v.z; rb[7]=c1v.w;
    }

    const int head = blockIdx.y * 4 + (tx >> 1);

#pragma unroll
    for (int i = 0; i < 4; ++i) {
        const int row   = ty4 + i;
        const int redge = r0 + row;
        const int sn = sidx[row];
        const int dn = sidx[BM + row];

        const float4* Kp = reinterpret_cast<const float4*>(g_Kh + (size_t)sn * CD + cbase + c0);
        const float4* Qp = reinterpret_cast<const float4*>(g_Qh + (size_t)dn * CD + cbase + c0);
        const float4* Vp = reinterpret_cast<const float4*>(g_Vh + (size_t)sn * CD + cbase + c0);
        float4 K0 = Kp[0], K1 = Kp[1];
        float4 Q0 = Qp[0], Q1 = Qp[1];
        float4 V0 = Vp[0], V1 = Vp[1];

        float kk8[8] = {K0.x, K0.y, K0.z, K0.w, K1.x, K1.y, K1.z, K1.w};
        float qq8[8] = {Q0.x, Q0.y, Q0.z, Q0.w, Q1.x, Q1.y, Q1.z, Q1.w};
        float vv8[8] = {V0.x, V0.y, V0.z, V0.w, V1.x, V1.y, V1.z, V1.w};

        float sc[8];
        float part = 0.f;
#pragma unroll
        for (int j = 0; j < 8; ++j) {
            float t = fmaf(kk8[j] * qq8[j], 0.25f, accR[i][j] + rb[j]);
            t = t * (accE[i][j] + eb[j]);
            sc[j] = t;
            part += t;
        }

        // streaming stores (write-once data, keep L2 for Qh/Kh/Vh)
        __stcs(reinterpret_cast<float4*>(out_e + (size_t)redge * CD + cbase + c0),
               make_float4(sc[0], sc[1], sc[2], sc[3]));
        __stcs(reinterpret_cast<float4*>(out_e + (size_t)redge * CD + cbase + c0 + 4),
               make_float4(sc[4], sc[5], sc[6], sc[7]));

        float tot = part + __shfl_xor_sync(0xffffffffu, part, 1);
        tot = fminf(fmaxf(tot, -5.0f), 5.0f);
        float sval = __expf(tot);

        float* w = out_h + (size_t)dn * CD + cbase + c0;
        red_add_v4(w,     vv8[0]*sval, vv8[1]*sval, vv8[2]*sval, vv8[3]*sval);
        red_add_v4(w + 4, vv8[4]*sval, vv8[5]*sval, vv8[6]*sval, vv8[7]*sval);
        if ((tx & 1) == 0) atomicAdd(&g_z[(size_t)dn * NH + head], sval);
    }
}

// ---------------- finalize: h_out = wV / (z + 1e-6) ----------------
__global__ __launch_bounds__(256) void finalize_kernel(float* __restrict__ out_h)
{
    int i = blockIdx.x * 256 + threadIdx.x;        // float4 index
    const int total = NN * CD / 4;
    if (i >= total) return;
    int n  = i >> 5;
    int cg = i & 31;
    int head = cg >> 2;
    float z = g_z[(size_t)n * NH + head] + 1e-6f;
    float inv = 1.0f / z;
    float4 v = reinterpret_cast<float4*>(out_h)[i];
    v.x *= inv; v.y *= inv; v.z *= inv; v.w *= inv;
    reinterpret_cast<float4*>(out_h)[i] = v;
}

// ---------------- launch ----------------
extern "C" void kernel_launch(void* const* d_in, const int* in_sizes, int n_in,
                              void* d_out, int out_size)
{
    const float* h   = (const float*)d_in[0];
    const float* e   = (const float*)d_in[1];
    const float* kr  = (const float*)d_in[2];
    const int*   src = (const int*)  d_in[3];
    const int*   dst = (const int*)  d_in[4];
    const float* Qw  = (const float*)d_in[5];
    const float* Qb  = (const float*)d_in[6];
    const float* Kw  = (const float*)d_in[7];
    const float* Kb  = (const float*)d_in[8];
    const float* Vw  = (const float*)d_in[9];
    const float* Vb  = (const float*)d_in[10];
    const float* Ew  = (const float*)d_in[11];
    const float* Eb  = (const float*)d_in[12];
    const float* Rw  = (const float*)d_in[13];
    const float* Rb  = (const float*)d_in[14];

    float* out_h = (float*)d_out;
    float* out_e = (float*)d_out + (size_t)NN * CD;

    const size_t NODE_SMEM = (size_t)(KDIM * CD + 64 * APAD) * 4;                   // ~99 KB
    const size_t EDGE_SMEM = (size_t)(2 * KDIM * BN + 2 * BM * ASTR) * 4 + 256 * 4; // ~101 KB

    cudaFuncSetAttribute(node_proj_qkv_kernel, cudaFuncAttributeMaxDynamicSharedMemorySize, (int)NODE_SMEM);
    cudaFuncSetAttribute(edge_kernel,          cudaFuncAttributeMaxDynamicSharedMemorySize, (int)EDGE_SMEM);

    cudaMemsetAsync(out_h, 0, (size_t)NN * CD * sizeof(float));
    void* zp = nullptr;
    cudaGetSymbolAddress(&zp, g_z);
    cudaMemsetAsync(zp, 0, (size_t)NN * NH * sizeof(float));

    void *qp, *kp, *vp;
    cudaGetSymbolAddress(&qp, g_Qh);
    cudaGetSymbolAddress(&kp, g_Kh);
    cudaGetSymbolAddress(&vp, g_Vh);

    const int nodeBlocks = (NN + 63) / 64;  // 782
    node_proj_qkv_kernel<<<nodeBlocks, 256, NODE_SMEM>>>(
        h, Qw, Qb, Kw, Kb, Vw, Vb, (float*)qp, (float*)kp, (float*)vp);

    dim3 eg(EE / BM, 2);                    // 6250 x 2
    edge_kernel<<<eg, 256, EDGE_SMEM>>>(e, kr, src, dst, Ew, Eb, Rw, Rb, out_h, out_e);

    const int finBlocks = (NN * CD / 4 + 255) / 256;
    finalize_kernel<<<finBlocks, 256>>>(out_h);
}

// round 6
// speedup vs baseline: 2.2743x; 1.2813x over previous
#include <cuda_runtime.h>
#include <cuda_bf16.h>
#include <mma.h>
#include <math.h>
#include <stdint.h>

using namespace nvcuda;

#define NN 50000
#define EE 800000
#define KDIM 128     // IN_DIM
#define CD 128       // H*D output cols
#define NH 8
#define HD 16
#define APAD 132

#define BM 128       // edges per block
#define BN 64        // cols per block (4 heads)
#define CHK 32       // K chunk
#define ALD 40       // A smem leading dim (bf16 elems)
#define BLD 72       // B smem leading dim (bf16 elems)
#define PLD 68       // proj smem leading dim (floats)

// ---------------- device scratch ----------------
__device__ float g_Qh[(size_t)NN * CD];
__device__ float g_Kh[(size_t)NN * CD];
__device__ float g_Vh[(size_t)NN * CD];
__device__ float g_z[(size_t)NN * NH];

__device__ __forceinline__ void red_add_v4(float* p, float a, float b, float c, float d) {
    asm volatile("red.global.add.v4.f32 [%0], {%1, %2, %3, %4};"
                 :: "l"(p), "f"(a), "f"(b), "f"(c), "f"(d) : "memory");
}

__device__ __forceinline__ void cvt_split(float x, __nv_bfloat16& hi, __nv_bfloat16& lo) {
    hi = __float2bfloat16(x);
    lo = __float2bfloat16(x - __bfloat162float(hi));
}

// smem layout (bytes)
#define SM_SIDX  0                        // 256 ints = 1024 B
#define SM_AEH   1024                     // 128*ALD bf16 = 10240
#define SM_AEL   (SM_AEH + BM * ALD * 2)
#define SM_AKH   (SM_AEL + BM * ALD * 2)
#define SM_AKL   (SM_AKH + BM * ALD * 2)
#define SM_BEH   (SM_AKL + BM * ALD * 2)  // 32*BLD bf16 = 4608
#define SM_BEL   (SM_BEH + CHK * BLD * 2)
#define SM_BRH   (SM_BEL + CHK * BLD * 2)
#define SM_BRL   (SM_BRH + CHK * BLD * 2)
#define SM_PROJ  (SM_BRL + CHK * BLD * 2) // 128*PLD float = 34816
#define SM_TOTAL (SM_PROJ + BM * PLD * 4) // = 95232

// ---------------- fused edge kernel: WMMA bf16 3-split dual GEMM ----------------
__global__ __launch_bounds__(256, 2) void edge_kernel(
    const float* __restrict__ e,
    const float* __restrict__ kr,
    const int*  __restrict__ src,
    const int*  __restrict__ dst,
    const float* __restrict__ Ew, const float* __restrict__ Eb,
    const float* __restrict__ Rw, const float* __restrict__ Rb,
    float* __restrict__ out_h,
    float* __restrict__ out_e)
{
    extern __shared__ char smem[];
    int*           sidx = reinterpret_cast<int*>(smem + SM_SIDX);
    __nv_bfloat16* sAEh = reinterpret_cast<__nv_bfloat16*>(smem + SM_AEH);
    __nv_bfloat16* sAEl = reinterpret_cast<__nv_bfloat16*>(smem + SM_AEL);
    __nv_bfloat16* sAKh = reinterpret_cast<__nv_bfloat16*>(smem + SM_AKH);
    __nv_bfloat16* sAKl = reinterpret_cast<__nv_bfloat16*>(smem + SM_AKL);
    __nv_bfloat16* sBEh = reinterpret_cast<__nv_bfloat16*>(smem + SM_BEH);
    __nv_bfloat16* sBEl = reinterpret_cast<__nv_bfloat16*>(smem + SM_BEL);
    __nv_bfloat16* sBRh = reinterpret_cast<__nv_bfloat16*>(smem + SM_BRH);
    __nv_bfloat16* sBRl = reinterpret_cast<__nv_bfloat16*>(smem + SM_BRL);
    float*         proj = reinterpret_cast<float*>(smem + SM_PROJ);

    const int tid = threadIdx.x;
    const int wid = tid >> 5;
    const int cbase = blockIdx.x * BN;     // col half on x (L2 reuse of e/kr)
    const int r0    = blockIdx.y * BM;

    if (tid < BM) {
        sidx[tid]      = src[r0 + tid];
        sidx[BM + tid] = dst[r0 + tid];
    }

    // warp tiling: warp_m = wid&3 (32 edges), warp_n = wid>>2 (32 cols)
    const int warp_m = wid & 3;
    const int warp_n = wid >> 2;

    wmma::fragment<wmma::accumulator, 16, 16, 16, float> accE[2][2], accR[2][2];
#pragma unroll
    for (int tm = 0; tm < 2; ++tm)
#pragma unroll
        for (int tn = 0; tn < 2; ++tn) {
            wmma::fill_fragment(accE[tm][tn], 0.0f);
            wmma::fill_fragment(accR[tm][tn], 0.0f);
        }

    for (int ch = 0; ch < KDIM / CHK; ++ch) {
        __syncthreads();
        // ---- convert A chunk (e, kr): 128 rows x 32 k -> bf16 hi/lo ----
        for (int i = tid; i < BM * (CHK / 4); i += 256) {
            int row = i >> 3, q = i & 7;
            int gk = ch * CHK + q * 4;
            float4 ve = *reinterpret_cast<const float4*>(e  + (size_t)(r0 + row) * KDIM + gk);
            float4 vk = *reinterpret_cast<const float4*>(kr + (size_t)(r0 + row) * KDIM + gk);
            const float ea[4] = {ve.x, ve.y, ve.z, ve.w};
            const float ka[4] = {vk.x, vk.y, vk.z, vk.w};
            int off = row * ALD + q * 4;
#pragma unroll
            for (int j = 0; j < 4; ++j) {
                __nv_bfloat16 h, l;
                cvt_split(ea[j], h, l);
                sAEh[off + j] = h; sAEl[off + j] = l;
                cvt_split(ka[j], h, l);
                sAKh[off + j] = h; sAKl[off + j] = l;
            }
        }
        // ---- convert B chunk (Ew, Rw): 32 k-rows x 64 cols -> bf16 hi/lo ----
        for (int i = tid; i < CHK * (BN / 4); i += 256) {
            int krow = i >> 4, q = i & 15;
            int gk = ch * CHK + krow;
            float4 we = *reinterpret_cast<const float4*>(Ew + (size_t)gk * CD + cbase + q * 4);
            float4 wr = *reinterpret_cast<const float4*>(Rw + (size_t)gk * CD + cbase + q * 4);
            const float ea[4] = {we.x, we.y, we.z, we.w};
            const float ra[4] = {wr.x, wr.y, wr.z, wr.w};
            int off = krow * BLD + q * 4;
#pragma unroll
            for (int j = 0; j < 4; ++j) {
                __nv_bfloat16 h, l;
                cvt_split(ea[j], h, l);
                sBEh[off + j] = h; sBEl[off + j] = l;
                cvt_split(ra[j], h, l);
                sBRh[off + j] = h; sBRl[off + j] = l;
            }
        }
        __syncthreads();

        // ---- WMMA: 2 k-steps of 16, 3 splits, dual matrices ----
#pragma unroll
        for (int ks = 0; ks < 2; ++ks) {
            wmma::fragment<wmma::matrix_a, 16, 16, 16, __nv_bfloat16, wmma::row_major> aH[2], aL[2];
            wmma::fragment<wmma::matrix_b, 16, 16, 16, __nv_bfloat16, wmma::row_major> bH[2], bL[2];
            // E matrix
#pragma unroll
            for (int tm = 0; tm < 2; ++tm) {
                const int arow = warp_m * 32 + tm * 16;
                wmma::load_matrix_sync(aH[tm], sAEh + arow * ALD + ks * 16, ALD);
                wmma::load_matrix_sync(aL[tm], sAEl + arow * ALD + ks * 16, ALD);
            }
#pragma unroll
            for (int tn = 0; tn < 2; ++tn) {
                const int bcol = warp_n * 32 + tn * 16;
                wmma::load_matrix_sync(bH[tn], sBEh + ks * 16 * BLD + bcol, BLD);
                wmma::load_matrix_sync(bL[tn], sBEl + ks * 16 * BLD + bcol, BLD);
            }
#pragma unroll
            for (int tm = 0; tm < 2; ++tm)
#pragma unroll
                for (int tn = 0; tn < 2; ++tn) {
                    wmma::mma_sync(accE[tm][tn], aH[tm], bH[tn], accE[tm][tn]);
                    wmma::mma_sync(accE[tm][tn], aH[tm], bL[tn], accE[tm][tn]);
                    wmma::mma_sync(accE[tm][tn], aL[tm], bH[tn], accE[tm][tn]);
                }
            // R matrix
#pragma unroll
            for (int tm = 0; tm < 2; ++tm) {
                const int arow = warp_m * 32 + tm * 16;
                wmma::load_matrix_sync(aH[tm], sAKh + arow * ALD + ks * 16, ALD);
                wmma::load_matrix_sync(aL[tm], sAKl + arow * ALD + ks * 16, ALD);
            }
#pragma unroll
            for (int tn = 0; tn < 2; ++tn) {
                const int bcol = warp_n * 32 + tn * 16;
                wmma::load_matrix_sync(bH[tn], sBRh + ks * 16 * BLD + bcol, BLD);
                wmma::load_matrix_sync(bL[tn], sBRl + ks * 16 * BLD + bcol, BLD);
            }
#pragma unroll
            for (int tm = 0; tm < 2; ++tm)
#pragma unroll
                for (int tn = 0; tn < 2; ++tn) {
                    wmma::mma_sync(accR[tm][tn], aH[tm], bH[tn], accR[tm][tn]);
                    wmma::mma_sync(accR[tm][tn], aH[tm], bL[tn], accR[tm][tn]);
                    wmma::mma_sync(accR[tm][tn], aL[tm], bH[tn], accR[tm][tn]);
                }
        }
    }

    // ---- epilogue ----
    const int erow = tid & 127;
    const int half = tid >> 7;            // 0: cols 0-31, 1: cols 32-63
    const int cc   = half * 32;
    const int gc   = cbase + cc;

    // stage E projection
    __syncthreads();
#pragma unroll
    for (int tm = 0; tm < 2; ++tm)
#pragma unroll
        for (int tn = 0; tn < 2; ++tn)
            wmma::store_matrix_sync(proj + (warp_m * 32 + tm * 16) * PLD + warp_n * 32 + tn * 16,
                                    accE[tm][tn], PLD, wmma::mem_row_major);
    __syncthreads();

    float pe[32];
#pragma unroll
    for (int q = 0; q < 8; ++q) {
        float4 v  = *reinterpret_cast<const float4*>(proj + erow * PLD + cc + q * 4);
        float4 bv = *reinterpret_cast<const float4*>(Eb + gc + q * 4);
        pe[q*4+0] = v.x + bv.x; pe[q*4+1] = v.y + bv.y;
        pe[q*4+2] = v.z + bv.z; pe[q*4+3] = v.w + bv.w;
    }
    __syncthreads();

    // stage R projection
#pragma unroll
    for (int tm = 0; tm < 2; ++tm)
#pragma unroll
        for (int tn = 0; tn < 2; ++tn)
            wmma::store_matrix_sync(proj + (warp_m * 32 + tm * 16) * PLD + warp_n * 32 + tn * 16,
                                    accR[tm][tn], PLD, wmma::mem_row_major);
    __syncthreads();

    float pr[32];
#pragma unroll
    for (int q = 0; q < 8; ++q) {
        float4 v  = *reinterpret_cast<const float4*>(proj + erow * PLD + cc + q * 4);
        float4 bv = *reinterpret_cast<const float4*>(Rb + gc + q * 4);
        pr[q*4+0] = v.x + bv.x; pr[q*4+1] = v.y + bv.y;
        pr[q*4+2] = v.z + bv.z; pr[q*4+3] = v.w + bv.w;
    }

    const int gedge = r0 + erow;
    const int sn = sidx[erow];
    const int dn = sidx[BM + erow];

    float sc[32], vv[32];
    float s0 = 0.f, s1 = 0.f;
#pragma unroll
    for (int q = 0; q < 8; ++q) {
        float4 kv = *reinterpret_cast<const float4*>(g_Kh + (size_t)sn * CD + gc + q * 4);
        float4 qv = *reinterpret_cast<const float4*>(g_Qh + (size_t)dn * CD + gc + q * 4);
        float4 v4 = *reinterpret_cast<const float4*>(g_Vh + (size_t)sn * CD + gc + q * 4);
        const float kk[4] = {kv.x, kv.y, kv.z, kv.w};
        const float qq[4] = {qv.x, qv.y, qv.z, qv.w};
        vv[q*4+0]=v4.x; vv[q*4+1]=v4.y; vv[q*4+2]=v4.z; vv[q*4+3]=v4.w;
#pragma unroll
        for (int j = 0; j < 4; ++j) {
            int idx = q * 4 + j;
            float t = fmaf(kk[j] * qq[j], 0.25f, pr[idx]) * pe[idx];
            sc[idx] = t;
            if (idx < 16) s0 += t; else s1 += t;
        }
    }

    float* oe = out_e + (size_t)gedge * CD + gc;
#pragma unroll
    for (int q = 0; q < 8; ++q)
        __stcs(reinterpret_cast<float4*>(oe + q * 4),
               make_float4(sc[q*4+0], sc[q*4+1], sc[q*4+2], sc[q*4+3]));

    s0 = __expf(fminf(fmaxf(s0, -5.0f), 5.0f));
    s1 = __expf(fminf(fmaxf(s1, -5.0f), 5.0f));

    float* w = out_h + (size_t)dn * CD + gc;
#pragma unroll
    for (int q = 0; q < 8; ++q) {
        float s = (q < 4) ? s0 : s1;
        red_add_v4(w + q * 4, vv[q*4+0]*s, vv[q*4+1]*s, vv[q*4+2]*s, vv[q*4+3]*s);
    }
    const int hbase = blockIdx.x * 4 + half * 2;
    atomicAdd(&g_z[(size_t)dn * NH + hbase],     s0);
    atomicAdd(&g_z[(size_t)dn * NH + hbase + 1], s1);
}

// ---------------- merged node projection: Q,K,V = h@W + b (R4, proven) ----------------
__global__ __launch_bounds__(256, 2) void node_proj_qkv_kernel(
    const float* __restrict__ h,
    const float* __restrict__ Qw, const float* __restrict__ Qb,
    const float* __restrict__ Kw, const float* __restrict__ Kb,
    const float* __restrict__ Vw, const float* __restrict__ Vb,
    float* __restrict__ outQ, float* __restrict__ outK, float* __restrict__ outV)
{
    extern __shared__ float sm[];
    float* sW = sm;                 // 128*128
    float* sA = sm + KDIM * CD;     // 64*APAD

    const int tid = threadIdx.x;
    const int r0  = blockIdx.x * 64;

    for (int i = tid; i < 64 * 32; i += 256) {
        int row = i >> 5, kc = i & 31;
        float4 v = make_float4(0.f, 0.f, 0.f, 0.f);
        int gr = r0 + row;
        if (gr < NN)
            v = reinterpret_cast<const float4*>(h + (size_t)gr * KDIM)[kc];
        *reinterpret_cast<float4*>(sA + row * APAD + kc * 4) = v;
    }

    const float* Ws[3] = {Qw, Kw, Vw};
    const float* Bs[3] = {Qb, Kb, Vb};
    float* Os[3] = {outQ, outK, outV};

    const int ty = tid >> 4, tx = tid & 15;
    const int c0 = tx * 8;
    const int ty4 = ty * 4;

    for (int m = 0; m < 3; ++m) {
        __syncthreads();
        const float* W = Ws[m];
        for (int i = tid; i < KDIM * CD / 4; i += 256)
            reinterpret_cast<float4*>(sW)[i] = reinterpret_cast<const float4*>(W)[i];
        __syncthreads();

        float acc[4][8];
#pragma unroll
        for (int i = 0; i < 4; ++i)
#pragma unroll
            for (int j = 0; j < 8; ++j) acc[i][j] = 0.f;

#pragma unroll
        for (int kg = 0; kg < KDIM / 4; ++kg) {
            float4 a4[4];
#pragma unroll
            for (int i = 0; i < 4; ++i)
                a4[i] = *reinterpret_cast<const float4*>(sA + (ty4 + i) * APAD + kg * 4);
#pragma unroll
            for (int kk = 0; kk < 4; ++kk) {
                const int k = kg * 4 + kk;
                float4 w0 = *reinterpret_cast<const float4*>(sW + k * CD + c0);
                float4 w1 = *reinterpret_cast<const float4*>(sW + k * CD + c0 + 4);
                float we[8] = {w0.x, w0.y, w0.z, w0.w, w1.x, w1.y, w1.z, w1.w};
#pragma unroll
                for (int i = 0; i < 4; ++i) {
                    float a = reinterpret_cast<const float*>(&a4[i])[kk];
#pragma unroll
                    for (int j = 0; j < 8; ++j) acc[i][j] = fmaf(a, we[j], acc[i][j]);
                }
            }
        }

        float bb[8];
        {
            float4 b0 = *reinterpret_cast<const float4*>(Bs[m] + c0);
            float4 b1 = *reinterpret_cast<const float4*>(Bs[m] + c0 + 4);
            bb[0]=b0.x; bb[1]=b0.y; bb[2]=b0.z; bb[3]=b0.w;
            bb[4]=b1.x; bb[5]=b1.y; bb[6]=b1.z; bb[7]=b1.w;
        }
        float* out = Os[m];
#pragma unroll
        for (int i = 0; i < 4; ++i) {
            int r = r0 + ty4 + i;
            if (r >= NN) continue;
            reinterpret_cast<float4*>(out + (size_t)r * CD + c0)[0] =
                make_float4(acc[i][0]+bb[0], acc[i][1]+bb[1], acc[i][2]+bb[2], acc[i][3]+bb[3]);
            reinterpret_cast<float4*>(out + (size_t)r * CD + c0 + 4)[0] =
                make_float4(acc[i][4]+bb[4], acc[i][5]+bb[5], acc[i][6]+bb[6], acc[i][7]+bb[7]);
        }
    }
}

// ---------------- finalize: h_out = wV / (z + 1e-6) ----------------
__global__ __launch_bounds__(256) void finalize_kernel(float* __restrict__ out_h)
{
    int i = blockIdx.x * 256 + threadIdx.x;        // float4 index
    const int total = NN * CD / 4;
    if (i >= total) return;
    int n  = i >> 5;
    int cg = i & 31;
    int head = cg >> 2;
    float z = g_z[(size_t)n * NH + head] + 1e-6f;
    float inv = 1.0f / z;
    float4 v = reinterpret_cast<float4*>(out_h)[i];
    v.x *= inv; v.y *= inv; v.z *= inv; v.w *= inv;
    reinterpret_cast<float4*>(out_h)[i] = v;
}

// ---------------- launch ----------------
extern "C" void kernel_launch(void* const* d_in, const int* in_sizes, int n_in,
                              void* d_out, int out_size)
{
    const float* h   = (const float*)d_in[0];
    const float* e   = (const float*)d_in[1];
    const float* kr  = (const float*)d_in[2];
    const int*   src = (const int*)  d_in[3];
    const int*   dst = (const int*)  d_in[4];
    const float* Qw  = (const float*)d_in[5];
    const float* Qb  = (const float*)d_in[6];
    const float* Kw  = (const float*)d_in[7];
    const float* Kb  = (const float*)d_in[8];
    const float* Vw  = (const float*)d_in[9];
    const float* Vb  = (const float*)d_in[10];
    const float* Ew  = (const float*)d_in[11];
    const float* Eb  = (const float*)d_in[12];
    const float* Rw  = (const float*)d_in[13];
    const float* Rb  = (const float*)d_in[14];

    float* out_h = (float*)d_out;
    float* out_e = (float*)d_out + (size_t)NN * CD;

    const size_t NODE_SMEM = (size_t)(KDIM * CD + 64 * APAD) * 4;   // ~99 KB
    const size_t EDGE_SMEM = SM_TOTAL;                              // 95232 B

    cudaFuncSetAttribute(node_proj_qkv_kernel, cudaFuncAttributeMaxDynamicSharedMemorySize, (int)NODE_SMEM);
    cudaFuncSetAttribute(edge_kernel,          cudaFuncAttributeMaxDynamicSharedMemorySize, (int)EDGE_SMEM);

    cudaMemsetAsync(out_h, 0, (size_t)NN * CD * sizeof(float));
    void* zp = nullptr;
    cudaGetSymbolAddress(&zp, g_z);
    cudaMemsetAsync(zp, 0, (size_t)NN * NH * sizeof(float));

    void *qp, *kp, *vp;
    cudaGetSymbolAddress(&qp, g_Qh);
    cudaGetSymbolAddress(&kp, g_Kh);
    cudaGetSymbolAddress(&vp, g_Vh);

    const int nodeBlocks = (NN + 63) / 64;  // 782
    node_proj_qkv_kernel<<<nodeBlocks, 256, NODE_SMEM>>>(
        h, Qw, Qb, Kw, Kb, Vw, Vb, (float*)qp, (float*)kp, (float*)vp);

    dim3 eg(2, EE / BM);                    // (col-half, edge blocks) — x fastest for L2 reuse
    edge_kernel<<<eg, 256, EDGE_SMEM>>>(e, kr, src, dst, Ew, Eb, Rw, Rb, out_h, out_e);

    const int finBlocks = (NN * CD / 4 + 255) / 256;
    finalize_kernel<<<finBlocks, 256>>>(out_h);
}

// round 7
// speedup vs baseline: 2.4318x; 1.0692x over previous
#include <cuda_runtime.h>
#include <cuda_bf16.h>
#include <mma.h>
#include <math.h>
#include <stdint.h>

using namespace nvcuda;

#define NN 50000
#define EE 800000
#define KDIM 128
#define CD 128
#define NH 8

#define BM 64        // edges per block (edge kernel)
#define CHK 32       // K chunk
#define ALD 40       // A smem leading dim for 32-k chunk (bf16)
#define AFULL 136    // A smem leading dim for full 128-k (bf16, node)
#define BLD 136      // B smem leading dim, 128 cols (bf16)
#define PLD 132      // proj smem leading dim (floats)

// ---------------- device scratch ----------------
__device__ float g_Qh[(size_t)NN * CD];
__device__ float g_Kh[(size_t)NN * CD];
__device__ float g_Vh[(size_t)NN * CD];
__device__ float g_z[(size_t)NN * NH];
// precomputed bf16 hi/lo weights: 0=Ew 1=Rw 2=Qw 3=Kw 4=Vw
__device__ __align__(16) __nv_bfloat16 g_WH[5][KDIM * CD];
__device__ __align__(16) __nv_bfloat16 g_WL[5][KDIM * CD];

__device__ __forceinline__ void red_add_v4(float* p, float a, float b, float c, float d) {
    asm volatile("red.global.add.v4.f32 [%0], {%1, %2, %3, %4};"
                 :: "l"(p), "f"(a), "f"(b), "f"(c), "f"(d) : "memory");
}
__device__ __forceinline__ void cvt_split(float x, __nv_bfloat16& hi, __nv_bfloat16& lo) {
    hi = __float2bfloat16(x);
    lo = __float2bfloat16(x - __bfloat162float(hi));
}

// ---------------- weight conversion (runs once per launch) ----------------
__global__ __launch_bounds__(256) void convert_weights_kernel(
    const float* __restrict__ Ew, const float* __restrict__ Rw,
    const float* __restrict__ Qw, const float* __restrict__ Kw,
    const float* __restrict__ Vw)
{
    int i = blockIdx.x * 256 + threadIdx.x;
    if (i >= KDIM * CD) return;
    const float* src[5] = {Ew, Rw, Qw, Kw, Vw};
#pragma unroll
    for (int m = 0; m < 5; ++m) {
        __nv_bfloat16 h, l;
        cvt_split(src[m][i], h, l);
        g_WH[m][i] = h;
        g_WL[m][i] = l;
    }
}

// ================= edge kernel: 64 edges x 128 cols, WMMA bf16 3-split =================
// smem map (bytes)
#define ESM_SIDX  0                           // 2*64 ints = 512
#define ESM_AEH   512
#define ESM_AEL   (ESM_AEH + BM * ALD * 2)    // 5120 each
#define ESM_AKH   (ESM_AEL + BM * ALD * 2)
#define ESM_AKL   (ESM_AKH + BM * ALD * 2)
#define ESM_BEH   (ESM_AKL + BM * ALD * 2)
#define ESM_BEL   (ESM_BEH + CHK * BLD * 2)   // 8704 each
#define ESM_BRH   (ESM_BEL + CHK * BLD * 2)
#define ESM_BRL   (ESM_BRH + CHK * BLD * 2)
#define ESM_PROJ  (ESM_BRL + CHK * BLD * 2)
#define ESM_TOTAL (ESM_PROJ + BM * PLD * 4)   // 89600

__global__ __launch_bounds__(256, 2) void edge_kernel(
    const float* __restrict__ e,
    const float* __restrict__ kr,
    const int*  __restrict__ src,
    const int*  __restrict__ dst,
    const float* __restrict__ Eb,
    const float* __restrict__ Rb,
    float* __restrict__ out_h,
    float* __restrict__ out_e)
{
    extern __shared__ char smem[];
    int*           sidx = reinterpret_cast<int*>(smem + ESM_SIDX);
    __nv_bfloat16* sAEh = reinterpret_cast<__nv_bfloat16*>(smem + ESM_AEH);
    __nv_bfloat16* sAEl = reinterpret_cast<__nv_bfloat16*>(smem + ESM_AEL);
    __nv_bfloat16* sAKh = reinterpret_cast<__nv_bfloat16*>(smem + ESM_AKH);
    __nv_bfloat16* sAKl = reinterpret_cast<__nv_bfloat16*>(smem + ESM_AKL);
    __nv_bfloat16* sBEh = reinterpret_cast<__nv_bfloat16*>(smem + ESM_BEH);
    __nv_bfloat16* sBEl = reinterpret_cast<__nv_bfloat16*>(smem + ESM_BEL);
    __nv_bfloat16* sBRh = reinterpret_cast<__nv_bfloat16*>(smem + ESM_BRH);
    __nv_bfloat16* sBRl = reinterpret_cast<__nv_bfloat16*>(smem + ESM_BRL);
    float*         proj = reinterpret_cast<float*>(smem + ESM_PROJ);

    const int tid = threadIdx.x;
    const int wid = tid >> 5;
    const int r0  = blockIdx.x * BM;

    if (tid < BM) {
        sidx[tid]      = src[r0 + tid];
        sidx[BM + tid] = dst[r0 + tid];
    }

    const int warp_m = wid & 1;    // 2 x 32 edges
    const int warp_n = wid >> 1;   // 4 x 32 cols

    wmma::fragment<wmma::accumulator, 16, 16, 16, float> accE[2][2], accR[2][2];
#pragma unroll
    for (int tm = 0; tm < 2; ++tm)
#pragma unroll
        for (int tn = 0; tn < 2; ++tn) {
            wmma::fill_fragment(accE[tm][tn], 0.0f);
            wmma::fill_fragment(accR[tm][tn], 0.0f);
        }

    for (int ch = 0; ch < KDIM / CHK; ++ch) {
        __syncthreads();
        // ---- convert A chunk (e, kr): 64 rows x 32 k ----
        for (int i = tid; i < BM * (CHK / 4); i += 256) {   // 512
            int row = i >> 3, q = i & 7;
            int gk = ch * CHK + q * 4;
            float4 ve = *reinterpret_cast<const float4*>(e  + (size_t)(r0 + row) * KDIM + gk);
            float4 vk = *reinterpret_cast<const float4*>(kr + (size_t)(r0 + row) * KDIM + gk);
            const float ea[4] = {ve.x, ve.y, ve.z, ve.w};
            const float ka[4] = {vk.x, vk.y, vk.z, vk.w};
            int off = row * ALD + q * 4;
#pragma unroll
            for (int j = 0; j < 4; ++j) {
                __nv_bfloat16 h, l;
                cvt_split(ea[j], h, l); sAEh[off + j] = h; sAEl[off + j] = l;
                cvt_split(ka[j], h, l); sAKh[off + j] = h; sAKl[off + j] = l;
            }
        }
        // ---- copy precomputed B chunk (Ew, Rw hi/lo): 32 k-rows x 128 cols ----
        for (int i = tid; i < CHK * (CD / 8); i += 256) {   // 512
            int krow = i >> 4, q = i & 15;
            size_t goff = (size_t)(ch * CHK + krow) * CD + q * 8;
            int soff = krow * BLD + q * 8;
            *reinterpret_cast<uint4*>(sBEh + soff) = *reinterpret_cast<const uint4*>(&g_WH[0][goff]);
            *reinterpret_cast<uint4*>(sBEl + soff) = *reinterpret_cast<const uint4*>(&g_WL[0][goff]);
            *reinterpret_cast<uint4*>(sBRh + soff) = *reinterpret_cast<const uint4*>(&g_WH[1][goff]);
            *reinterpret_cast<uint4*>(sBRl + soff) = *reinterpret_cast<const uint4*>(&g_WL[1][goff]);
        }
        __syncthreads();

#pragma unroll
        for (int ks = 0; ks < 2; ++ks) {
            wmma::fragment<wmma::matrix_a, 16, 16, 16, __nv_bfloat16, wmma::row_major> aH[2], aL[2];
            wmma::fragment<wmma::matrix_b, 16, 16, 16, __nv_bfloat16, wmma::row_major> bH[2], bL[2];
            // E
#pragma unroll
            for (int tm = 0; tm < 2; ++tm) {
                const int ar = warp_m * 32 + tm * 16;
                wmma::load_matrix_sync(aH[tm], sAEh + ar * ALD + ks * 16, ALD);
                wmma::load_matrix_sync(aL[tm], sAEl + ar * ALD + ks * 16, ALD);
            }
#pragma unroll
            for (int tn = 0; tn < 2; ++tn) {
                const int bc = warp_n * 32 + tn * 16;
                wmma::load_matrix_sync(bH[tn], sBEh + ks * 16 * BLD + bc, BLD);
                wmma::load_matrix_sync(bL[tn], sBEl + ks * 16 * BLD + bc, BLD);
            }
#pragma unroll
            for (int tm = 0; tm < 2; ++tm)
#pragma unroll
                for (int tn = 0; tn < 2; ++tn) {
                    wmma::mma_sync(accE[tm][tn], aH[tm], bH[tn], accE[tm][tn]);
                    wmma::mma_sync(accE[tm][tn], aH[tm], bL[tn], accE[tm][tn]);
                    wmma::mma_sync(accE[tm][tn], aL[tm], bH[tn], accE[tm][tn]);
                }
            // R
#pragma unroll
            for (int tm = 0; tm < 2; ++tm) {
                const int ar = warp_m * 32 + tm * 16;
                wmma::load_matrix_sync(aH[tm], sAKh + ar * ALD + ks * 16, ALD);
                wmma::load_matrix_sync(aL[tm], sAKl + ar * ALD + ks * 16, ALD);
            }
#pragma unroll
            for (int tn = 0; tn < 2; ++tn) {
                const int bc = warp_n * 32 + tn * 16;
                wmma::load_matrix_sync(bH[tn], sBRh + ks * 16 * BLD + bc, BLD);
                wmma::load_matrix_sync(bL[tn], sBRl + ks * 16 * BLD + bc, BLD);
            }
#pragma unroll
            for (int tm = 0; tm < 2; ++tm)
#pragma unroll
                for (int tn = 0; tn < 2; ++tn) {
                    wmma::mma_sync(accR[tm][tn], aH[tm], bH[tn], accR[tm][tn]);
                    wmma::mma_sync(accR[tm][tn], aH[tm], bL[tn], accR[tm][tn]);
                    wmma::mma_sync(accR[tm][tn], aL[tm], bH[tn], accR[tm][tn]);
                }
        }
    }

    // ---- epilogue: thread = (edge, 32-col quarter) ----
    const int erow    = tid & 63;
    const int quarter = tid >> 6;          // 0..3 -> cols 32*q
    const int cc      = quarter * 32;

    // stage R projection, hold in regs
    __syncthreads();
#pragma unroll
    for (int tm = 0; tm < 2; ++tm)
#pragma unroll
        for (int tn = 0; tn < 2; ++tn)
            wmma::store_matrix_sync(proj + (warp_m * 32 + tm * 16) * PLD + warp_n * 32 + tn * 16,
                                    accR[tm][tn], PLD, wmma::mem_row_major);
    __syncthreads();

    float pr[32];
#pragma unroll
    for (int q = 0; q < 8; ++q) {
        float4 v  = *reinterpret_cast<const float4*>(proj + erow * PLD + cc + q * 4);
        float4 bv = *reinterpret_cast<const float4*>(Rb + cc + q * 4);
        pr[q*4+0] = v.x + bv.x; pr[q*4+1] = v.y + bv.y;
        pr[q*4+2] = v.z + bv.z; pr[q*4+3] = v.w + bv.w;
    }
    __syncthreads();

    // stage E projection
#pragma unroll
    for (int tm = 0; tm < 2; ++tm)
#pragma unroll
        for (int tn = 0; tn < 2; ++tn)
            wmma::store_matrix_sync(proj + (warp_m * 32 + tm * 16) * PLD + warp_n * 32 + tn * 16,
                                    accE[tm][tn], PLD, wmma::mem_row_major);
    __syncthreads();

    const int gedge = r0 + erow;
    const int sn = sidx[erow];
    const int dn = sidx[BM + erow];

    float vv[32];
    float s0 = 0.f, s1 = 0.f;
    float* oe = out_e + (size_t)gedge * CD + cc;
#pragma unroll
    for (int q = 0; q < 8; ++q) {
        float4 pv = *reinterpret_cast<const float4*>(proj + erow * PLD + cc + q * 4);
        float4 bv = *reinterpret_cast<const float4*>(Eb + cc + q * 4);
        float4 kv = *reinterpret_cast<const float4*>(g_Kh + (size_t)sn * CD + cc + q * 4);
        float4 qv = *reinterpret_cast<const float4*>(g_Qh + (size_t)dn * CD + cc + q * 4);
        float4 v4 = *reinterpret_cast<const float4*>(g_Vh + (size_t)sn * CD + cc + q * 4);
        vv[q*4+0]=v4.x; vv[q*4+1]=v4.y; vv[q*4+2]=v4.z; vv[q*4+3]=v4.w;
        const float pe[4] = {pv.x + bv.x, pv.y + bv.y, pv.z + bv.z, pv.w + bv.w};
        const float kk[4] = {kv.x, kv.y, kv.z, kv.w};
        const float qq[4] = {qv.x, qv.y, qv.z, qv.w};
        float sc[4];
#pragma unroll
        for (int j = 0; j < 4; ++j) {
            float t = fmaf(kk[j] * qq[j], 0.25f, pr[q*4+j]) * pe[j];
            sc[j] = t;
            if (q < 4) s0 += t; else s1 += t;
        }
        __stcs(reinterpret_cast<float4*>(oe + q * 4), make_float4(sc[0], sc[1], sc[2], sc[3]));
    }

    s0 = __expf(fminf(fmaxf(s0, -5.0f), 5.0f));
    s1 = __expf(fminf(fmaxf(s1, -5.0f), 5.0f));

    float* w = out_h + (size_t)dn * CD + cc;
#pragma unroll
    for (int q = 0; q < 8; ++q) {
        float s = (q < 4) ? s0 : s1;
        red_add_v4(w + q * 4, vv[q*4+0]*s, vv[q*4+1]*s, vv[q*4+2]*s, vv[q*4+3]*s);
    }
    const int hbase = quarter * 2;
    atomicAdd(&g_z[(size_t)dn * NH + hbase],     s0);
    atomicAdd(&g_z[(size_t)dn * NH + hbase + 1], s1);
}

// ================= node kernel: 64 nodes x 128 cols x 3 matrices, WMMA =================
#define NSM_AH   0
#define NSM_AL   (NSM_AH + 64 * AFULL * 2)    // 17408 each
#define NSM_BH   (NSM_AL + 64 * AFULL * 2)
#define NSM_BL   (NSM_BH + CHK * BLD * 2)     // 8704 each
#define NSM_PROJ (NSM_BL + CHK * BLD * 2)
#define NSM_TOTAL (NSM_PROJ + 64 * PLD * 4)   // 86016

__global__ __launch_bounds__(256, 2) void node_proj_qkv_kernel(
    const float* __restrict__ h,
    const float* __restrict__ Qb, const float* __restrict__ Kb, const float* __restrict__ Vb,
    float* __restrict__ outQ, float* __restrict__ outK, float* __restrict__ outV)
{
    extern __shared__ char smem[];
    __nv_bfloat16* sAH = reinterpret_cast<__nv_bfloat16*>(smem + NSM_AH);
    __nv_bfloat16* sAL = reinterpret_cast<__nv_bfloat16*>(smem + NSM_AL);
    __nv_bfloat16* sBH = reinterpret_cast<__nv_bfloat16*>(smem + NSM_BH);
    __nv_bfloat16* sBL = reinterpret_cast<__nv_bfloat16*>(smem + NSM_BL);
    float*        proj = reinterpret_cast<float*>(smem + NSM_PROJ);

    const int tid = threadIdx.x;
    const int wid = tid >> 5;
    const int r0  = blockIdx.x * 64;

    // convert full A (h rows) once: 64 x 128
    for (int i = tid; i < 64 * 32; i += 256) {
        int row = i >> 5, kq = i & 31;
        float4 v = make_float4(0.f, 0.f, 0.f, 0.f);
        if (r0 + row < NN)
            v = reinterpret_cast<const float4*>(h + (size_t)(r0 + row) * KDIM)[kq];
        const float a[4] = {v.x, v.y, v.z, v.w};
        int off = row * AFULL + kq * 4;
#pragma unroll
        for (int j = 0; j < 4; ++j) {
            __nv_bfloat16 hh, ll;
            cvt_split(a[j], hh, ll);
            sAH[off + j] = hh; sAL[off + j] = ll;
        }
    }

    const float* Bs[3] = {Qb, Kb, Vb};
    float* Os[3] = {outQ, outK, outV};
    const int widx[3] = {2, 3, 4};   // g_WH indices for Qw, Kw, Vw

    const int warp_m = wid & 1;
    const int warp_n = wid >> 1;

    for (int m = 0; m < 3; ++m) {
        wmma::fragment<wmma::accumulator, 16, 16, 16, float> acc[2][2];
#pragma unroll
        for (int tm = 0; tm < 2; ++tm)
#pragma unroll
            for (int tn = 0; tn < 2; ++tn) wmma::fill_fragment(acc[tm][tn], 0.0f);

        for (int ch = 0; ch < KDIM / CHK; ++ch) {
            __syncthreads();
            for (int i = tid; i < CHK * (CD / 8); i += 256) {
                int krow = i >> 4, q = i & 15;
                size_t goff = (size_t)(ch * CHK + krow) * CD + q * 8;
                int soff = krow * BLD + q * 8;
                *reinterpret_cast<uint4*>(sBH + soff) = *reinterpret_cast<const uint4*>(&g_WH[widx[m]][goff]);
                *reinterpret_cast<uint4*>(sBL + soff) = *reinterpret_cast<const uint4*>(&g_WL[widx[m]][goff]);
            }
            __syncthreads();

#pragma unroll
            for (int ks = 0; ks < 2; ++ks) {
                wmma::fragment<wmma::matrix_a, 16, 16, 16, __nv_bfloat16, wmma::row_major> aH[2], aL[2];
                wmma::fragment<wmma::matrix_b, 16, 16, 16, __nv_bfloat16, wmma::row_major> bH[2], bL[2];
#pragma unroll
                for (int tm = 0; tm < 2; ++tm) {
                    const int ar = warp_m * 32 + tm * 16;
                    wmma::load_matrix_sync(aH[tm], sAH + ar * AFULL + ch * CHK + ks * 16, AFULL);
                    wmma::load_matrix_sync(aL[tm], sAL + ar * AFULL + ch * CHK + ks * 16, AFULL);
                }
#pragma unroll
                for (int tn = 0; tn < 2; ++tn) {
                    const int bc = warp_n * 32 + tn * 16;
                    wmma::load_matrix_sync(bH[tn], sBH + ks * 16 * BLD + bc, BLD);
                    wmma::load_matrix_sync(bL[tn], sBL + ks * 16 * BLD + bc, BLD);
                }
#pragma unroll
                for (int tm = 0; tm < 2; ++tm)
#pragma unroll
                    for (int tn = 0; tn < 2; ++tn) {
                        wmma::mma_sync(acc[tm][tn], aH[tm], bH[tn], acc[tm][tn]);
                        wmma::mma_sync(acc[tm][tn], aH[tm], bL[tn], acc[tm][tn]);
                        wmma::mma_sync(acc[tm][tn], aL[tm], bH[tn], acc[tm][tn]);
                    }
            }
        }

        __syncthreads();
#pragma unroll
        for (int tm = 0; tm < 2; ++tm)
#pragma unroll
            for (int tn = 0; tn < 2; ++tn)
                wmma::store_matrix_sync(proj + (warp_m * 32 + tm * 16) * PLD + warp_n * 32 + tn * 16,
                                        acc[tm][tn], PLD, wmma::mem_row_major);
        __syncthreads();

        // write out: 64 rows x 128 cols, thread = (row, 32-col quarter)
        const int row = tid >> 2;
        const int cq  = (tid & 3) * 32;
        if (r0 + row < NN) {
            float* out = Os[m] + (size_t)(r0 + row) * CD + cq;
#pragma unroll
            for (int q = 0; q < 8; ++q) {
                float4 v  = *reinterpret_cast<const float4*>(proj + row * PLD + cq + q * 4);
                float4 bv = *reinterpret_cast<const float4*>(Bs[m] + cq + q * 4);
                reinterpret_cast<float4*>(out + q * 4)[0] =
                    make_float4(v.x + bv.x, v.y + bv.y, v.z + bv.z, v.w + bv.w);
            }
        }
    }
}

// ---------------- finalize: h_out = wV / (z + 1e-6) ----------------
__global__ __launch_bounds__(256) void finalize_kernel(float* __restrict__ out_h)
{
    int i = blockIdx.x * 256 + threadIdx.x;
    const int total = NN * CD / 4;
    if (i >= total) return;
    int n  = i >> 5;
    int cg = i & 31;
    int head = cg >> 2;
    float z = g_z[(size_t)n * NH + head] + 1e-6f;
    float inv = 1.0f / z;
    float4 v = reinterpret_cast<float4*>(out_h)[i];
    v.x *= inv; v.y *= inv; v.z *= inv; v.w *= inv;
    reinterpret_cast<float4*>(out_h)[i] = v;
}

// ---------------- launch ----------------
extern "C" void kernel_launch(void* const* d_in, const int* in_sizes, int n_in,
                              void* d_out, int out_size)
{
    const float* h   = (const float*)d_in[0];
    const float* e   = (const float*)d_in[1];
    const float* kr  = (const float*)d_in[2];
    const int*   src = (const int*)  d_in[3];
    const int*   dst = (const int*)  d_in[4];
    const float* Qw  = (const float*)d_in[5];
    const float* Qb  = (const float*)d_in[6];
    const float* Kw  = (const float*)d_in[7];
    const float* Kb  = (const float*)d_in[8];
    const float* Vw  = (const float*)d_in[9];
    const float* Vb  = (const float*)d_in[10];
    const float* Ew  = (const float*)d_in[11];
    const float* Eb  = (const float*)d_in[12];
    const float* Rw  = (const float*)d_in[13];
    const float* Rb  = (const float*)d_in[14];

    float* out_h = (float*)d_out;
    float* out_e = (float*)d_out + (size_t)NN * CD;

    cudaFuncSetAttribute(node_proj_qkv_kernel, cudaFuncAttributeMaxDynamicSharedMemorySize, NSM_TOTAL);
    cudaFuncSetAttribute(edge_kernel,          cudaFuncAttributeMaxDynamicSharedMemorySize, ESM_TOTAL);

    cudaMemsetAsync(out_h, 0, (size_t)NN * CD * sizeof(float));
    void* zp = nullptr;
    cudaGetSymbolAddress(&zp, g_z);
    cudaMemsetAsync(zp, 0, (size_t)NN * NH * sizeof(float));

    void *qp, *kp, *vp;
    cudaGetSymbolAddress(&qp, g_Qh);
    cudaGetSymbolAddress(&kp, g_Kh);
    cudaGetSymbolAddress(&vp, g_Vh);

    convert_weights_kernel<<<(KDIM * CD + 255) / 256, 256>>>(Ew, Rw, Qw, Kw, Vw);

    const int nodeBlocks = (NN + 63) / 64;  // 782
    node_proj_qkv_kernel<<<nodeBlocks, 256, NSM_TOTAL>>>(
        h, Qb, Kb, Vb, (float*)qp, (float*)kp, (float*)vp);

    edge_kernel<<<EE / BM, 256, ESM_TOTAL>>>(e, kr, src, dst, Eb, Rb, out_h, out_e);

    const int finBlocks = (NN * CD / 4 + 255) / 256;
    finalize_kernel<<<finBlocks, 256>>>(out_h);
}

// round 8
// speedup vs baseline: 2.5566x; 1.0514x over previous
#include <cuda_runtime.h>
#include <cuda_bf16.h>
#include <mma.h>
#include <math.h>
#include <stdint.h>

using namespace nvcuda;

#define NN 50000
#define EE 800000
#define KDIM 128
#define CD 128
#define NH 8

#define BM 64        // edges per block (edge kernel)
#define CHK 32       // K chunk
#define ALD 40       // A smem leading dim for 32-k chunk (bf16)
#define AFULL 136    // A smem leading dim for full 128-k (bf16, node)
#define BLD 136      // B smem leading dim, 128 cols (bf16)
#define PLD 132      // proj smem leading dim (floats)

// ---------------- device scratch ----------------
__device__ float g_Qh[(size_t)NN * CD];
__device__ float g_Kh[(size_t)NN * CD];
__device__ float g_Vh[(size_t)NN * CD];
__device__ float g_z[(size_t)NN * NH];
// precomputed bf16 hi/lo weights: 0=Ew 1=Rw 2=Qw 3=Kw 4=Vw
__device__ __align__(16) __nv_bfloat16 g_WH[5][KDIM * CD];
__device__ __align__(16) __nv_bfloat16 g_WL[5][KDIM * CD];

__device__ __forceinline__ void red_add_v4(float* p, float a, float b, float c, float d) {
    asm volatile("red.global.add.v4.f32 [%0], {%1, %2, %3, %4};"
                 :: "l"(p), "f"(a), "f"(b), "f"(c), "f"(d) : "memory");
}
__device__ __forceinline__ void cvt_split(float x, __nv_bfloat16& hi, __nv_bfloat16& lo) {
    hi = __float2bfloat16(x);
    lo = __float2bfloat16(x - __bfloat162float(hi));
}

// ---------------- weight conversion (runs once per launch) ----------------
__global__ __launch_bounds__(256) void convert_weights_kernel(
    const float* __restrict__ Ew, const float* __restrict__ Rw,
    const float* __restrict__ Qw, const float* __restrict__ Kw,
    const float* __restrict__ Vw)
{
    int i = blockIdx.x * 256 + threadIdx.x;
    if (i >= KDIM * CD) return;
    const float* src[5] = {Ew, Rw, Qw, Kw, Vw};
#pragma unroll
    for (int m = 0; m < 5; ++m) {
        __nv_bfloat16 h, l;
        cvt_split(src[m][i], h, l);
        g_WH[m][i] = h;
        g_WL[m][i] = l;
    }
}

// ================= edge kernel: 64 edges x 128 cols, WMMA bf16 3-split =================
// smem map (bytes)
#define ESM_SIDX  0                           // 2*64 ints = 512
#define ESM_AEH   512
#define ESM_AEL   (ESM_AEH + BM * ALD * 2)    // 5120 each
#define ESM_AKH   (ESM_AEL + BM * ALD * 2)
#define ESM_AKL   (ESM_AKH + BM * ALD * 2)
#define ESM_BEH   (ESM_AKL + BM * ALD * 2)
#define ESM_BEL   (ESM_BEH + CHK * BLD * 2)   // 8704 each
#define ESM_BRH   (ESM_BEL + CHK * BLD * 2)
#define ESM_BRL   (ESM_BRH + CHK * BLD * 2)
#define ESM_PROJ  (ESM_BRL + CHK * BLD * 2)
#define ESM_TOTAL (ESM_PROJ + BM * PLD * 4)   // 89600
// projE aliases the B tile region (34816 B >= 33792 B needed), dead after last MMA

__global__ __launch_bounds__(256, 2) void edge_kernel(
    const float* __restrict__ e,
    const float* __restrict__ kr,
    const int*  __restrict__ src,
    const int*  __restrict__ dst,
    const float* __restrict__ Eb,
    const float* __restrict__ Rb,
    float* __restrict__ out_h,
    float* __restrict__ out_e)
{
    extern __shared__ char smem[];
    int*           sidx = reinterpret_cast<int*>(smem + ESM_SIDX);
    __nv_bfloat16* sAEh = reinterpret_cast<__nv_bfloat16*>(smem + ESM_AEH);
    __nv_bfloat16* sAEl = reinterpret_cast<__nv_bfloat16*>(smem + ESM_AEL);
    __nv_bfloat16* sAKh = reinterpret_cast<__nv_bfloat16*>(smem + ESM_AKH);
    __nv_bfloat16* sAKl = reinterpret_cast<__nv_bfloat16*>(smem + ESM_AKL);
    __nv_bfloat16* sBEh = reinterpret_cast<__nv_bfloat16*>(smem + ESM_BEH);
    __nv_bfloat16* sBEl = reinterpret_cast<__nv_bfloat16*>(smem + ESM_BEL);
    __nv_bfloat16* sBRh = reinterpret_cast<__nv_bfloat16*>(smem + ESM_BRH);
    __nv_bfloat16* sBRl = reinterpret_cast<__nv_bfloat16*>(smem + ESM_BRL);
    float*         projR = reinterpret_cast<float*>(smem + ESM_PROJ);
    float*         projE = reinterpret_cast<float*>(smem + ESM_BEH);   // alias, safe post-MMA

    const int tid = threadIdx.x;
    const int wid = tid >> 5;
    const int r0  = blockIdx.x * BM;

    if (tid < BM) {
        sidx[tid]      = src[r0 + tid];
        sidx[BM + tid] = dst[r0 + tid];
    }

    const int warp_m = wid & 1;    // 2 x 32 edges
    const int warp_n = wid >> 1;   // 4 x 32 cols

    // A-fill thread mapping: 2 items per thread
    const int arow0 = tid >> 3;          // 0..31
    const int aq    = tid & 7;           // float4 index in k-chunk

    wmma::fragment<wmma::accumulator, 16, 16, 16, float> accE[2][2], accR[2][2];
#pragma unroll
    for (int tm = 0; tm < 2; ++tm)
#pragma unroll
        for (int tn = 0; tn < 2; ++tn) {
            wmma::fill_fragment(accE[tm][tn], 0.0f);
            wmma::fill_fragment(accR[tm][tn], 0.0f);
        }

    // prologue: prefetch chunk 0 e/kr to registers
    float4 pve[2], pvk[2];
#pragma unroll
    for (int it = 0; it < 2; ++it) {
        const int row = arow0 + 32 * it;
        pve[it] = *reinterpret_cast<const float4*>(e  + (size_t)(r0 + row) * KDIM + aq * 4);
        pvk[it] = *reinterpret_cast<const float4*>(kr + (size_t)(r0 + row) * KDIM + aq * 4);
    }

    for (int ch = 0; ch < KDIM / CHK; ++ch) {
        if (ch > 0) __syncthreads();     // prior MMA done reading smem tiles
        // ---- convert prefetched A regs -> smem ----
#pragma unroll
        for (int it = 0; it < 2; ++it) {
            const int row = arow0 + 32 * it;
            const int off = row * ALD + aq * 4;
            const float ea[4] = {pve[it].x, pve[it].y, pve[it].z, pve[it].w};
            const float ka[4] = {pvk[it].x, pvk[it].y, pvk[it].z, pvk[it].w};
#pragma unroll
            for (int j = 0; j < 4; ++j) {
                __nv_bfloat16 h, l;
                cvt_split(ea[j], h, l); sAEh[off + j] = h; sAEl[off + j] = l;
                cvt_split(ka[j], h, l); sAKh[off + j] = h; sAKl[off + j] = l;
            }
        }
        // ---- copy precomputed B chunk (L2-resident) ----
#pragma unroll
        for (int i = tid; i < CHK * (CD / 8); i += 256) {   // 512 -> 2 iters
            int krow = i >> 4, q = i & 15;
            size_t goff = (size_t)(ch * CHK + krow) * CD + q * 8;
            int soff = krow * BLD + q * 8;
            *reinterpret_cast<uint4*>(sBEh + soff) = *reinterpret_cast<const uint4*>(&g_WH[0][goff]);
            *reinterpret_cast<uint4*>(sBEl + soff) = *reinterpret_cast<const uint4*>(&g_WL[0][goff]);
            *reinterpret_cast<uint4*>(sBRh + soff) = *reinterpret_cast<const uint4*>(&g_WH[1][goff]);
            *reinterpret_cast<uint4*>(sBRl + soff) = *reinterpret_cast<const uint4*>(&g_WL[1][goff]);
        }
        __syncthreads();

        // ---- prefetch NEXT chunk's A while MMAs run ----
        if (ch < KDIM / CHK - 1) {
            const int gk = (ch + 1) * CHK + aq * 4;
#pragma unroll
            for (int it = 0; it < 2; ++it) {
                const int row = arow0 + 32 * it;
                pve[it] = *reinterpret_cast<const float4*>(e  + (size_t)(r0 + row) * KDIM + gk);
                pvk[it] = *reinterpret_cast<const float4*>(kr + (size_t)(r0 + row) * KDIM + gk);
            }
        }

#pragma unroll
        for (int ks = 0; ks < 2; ++ks) {
            wmma::fragment<wmma::matrix_a, 16, 16, 16, __nv_bfloat16, wmma::row_major> aH[2], aL[2];
            wmma::fragment<wmma::matrix_b, 16, 16, 16, __nv_bfloat16, wmma::row_major> bH[2], bL[2];
            // E
#pragma unroll
            for (int tm = 0; tm < 2; ++tm) {
                const int ar = warp_m * 32 + tm * 16;
                wmma::load_matrix_sync(aH[tm], sAEh + ar * ALD + ks * 16, ALD);
                wmma::load_matrix_sync(aL[tm], sAEl + ar * ALD + ks * 16, ALD);
            }
#pragma unroll
            for (int tn = 0; tn < 2; ++tn) {
                const int bc = warp_n * 32 + tn * 16;
                wmma::load_matrix_sync(bH[tn], sBEh + ks * 16 * BLD + bc, BLD);
                wmma::load_matrix_sync(bL[tn], sBEl + ks * 16 * BLD + bc, BLD);
            }
#pragma unroll
            for (int tm = 0; tm < 2; ++tm)
#pragma unroll
                for (int tn = 0; tn < 2; ++tn) {
                    wmma::mma_sync(accE[tm][tn], aH[tm], bH[tn], accE[tm][tn]);
                    wmma::mma_sync(accE[tm][tn], aH[tm], bL[tn], accE[tm][tn]);
                    wmma::mma_sync(accE[tm][tn], aL[tm], bH[tn], accE[tm][tn]);
                }
            // R
#pragma unroll
            for (int tm = 0; tm < 2; ++tm) {
                const int ar = warp_m * 32 + tm * 16;
                wmma::load_matrix_sync(aH[tm], sAKh + ar * ALD + ks * 16, ALD);
                wmma::load_matrix_sync(aL[tm], sAKl + ar * ALD + ks * 16, ALD);
            }
#pragma unroll
            for (int tn = 0; tn < 2; ++tn) {
                const int bc = warp_n * 32 + tn * 16;
                wmma::load_matrix_sync(bH[tn], sBRh + ks * 16 * BLD + bc, BLD);
                wmma::load_matrix_sync(bL[tn], sBRl + ks * 16 * BLD + bc, BLD);
            }
#pragma unroll
            for (int tm = 0; tm < 2; ++tm)
#pragma unroll
                for (int tn = 0; tn < 2; ++tn) {
                    wmma::mma_sync(accR[tm][tn], aH[tm], bH[tn], accR[tm][tn]);
                    wmma::mma_sync(accR[tm][tn], aH[tm], bL[tn], accR[tm][tn]);
                    wmma::mma_sync(accR[tm][tn], aL[tm], bH[tn], accR[tm][tn]);
                }
        }
    }

    // ---- epilogue: single staging pass (projE aliases dead B tiles) ----
    __syncthreads();
#pragma unroll
    for (int tm = 0; tm < 2; ++tm)
#pragma unroll
        for (int tn = 0; tn < 2; ++tn) {
            const int po = (warp_m * 32 + tm * 16) * PLD + warp_n * 32 + tn * 16;
            wmma::store_matrix_sync(projR + po, accR[tm][tn], PLD, wmma::mem_row_major);
            wmma::store_matrix_sync(projE + po, accE[tm][tn], PLD, wmma::mem_row_major);
        }
    __syncthreads();

    const int erow    = tid & 63;
    const int quarter = tid >> 6;          // 0..3 -> cols 32*q
    const int cc      = quarter * 32;

    const int gedge = r0 + erow;
    const int sn = sidx[erow];
    const int dn = sidx[BM + erow];

    float vv[32];
    float s0 = 0.f, s1 = 0.f;
    float* oe = out_e + (size_t)gedge * CD + cc;
#pragma unroll
    for (int q = 0; q < 8; ++q) {
        float4 rv = *reinterpret_cast<const float4*>(projR + erow * PLD + cc + q * 4);
        float4 rbv = *reinterpret_cast<const float4*>(Rb + cc + q * 4);
        float4 ev = *reinterpret_cast<const float4*>(projE + erow * PLD + cc + q * 4);
        float4 ebv = *reinterpret_cast<const float4*>(Eb + cc + q * 4);
        float4 kv = *reinterpret_cast<const float4*>(g_Kh + (size_t)sn * CD + cc + q * 4);
        float4 qv = *reinterpret_cast<const float4*>(g_Qh + (size_t)dn * CD + cc + q * 4);
        float4 v4 = *reinterpret_cast<const float4*>(g_Vh + (size_t)sn * CD + cc + q * 4);
        vv[q*4+0]=v4.x; vv[q*4+1]=v4.y; vv[q*4+2]=v4.z; vv[q*4+3]=v4.w;
        const float pr[4] = {rv.x + rbv.x, rv.y + rbv.y, rv.z + rbv.z, rv.w + rbv.w};
        const float pe[4] = {ev.x + ebv.x, ev.y + ebv.y, ev.z + ebv.z, ev.w + ebv.w};
        const float kk[4] = {kv.x, kv.y, kv.z, kv.w};
        const float qq[4] = {qv.x, qv.y, qv.z, qv.w};
        float sc[4];
#pragma unroll
        for (int j = 0; j < 4; ++j) {
            float t = fmaf(kk[j] * qq[j], 0.25f, pr[j]) * pe[j];
            sc[j] = t;
            if (q < 4) s0 += t; else s1 += t;
        }
        __stcs(reinterpret_cast<float4*>(oe + q * 4), make_float4(sc[0], sc[1], sc[2], sc[3]));
    }

    s0 = __expf(fminf(fmaxf(s0, -5.0f), 5.0f));
    s1 = __expf(fminf(fmaxf(s1, -5.0f), 5.0f));

    float* w = out_h + (size_t)dn * CD + cc;
#pragma unroll
    for (int q = 0; q < 8; ++q) {
        float s = (q < 4) ? s0 : s1;
        red_add_v4(w + q * 4, vv[q*4+0]*s, vv[q*4+1]*s, vv[q*4+2]*s, vv[q*4+3]*s);
    }
    const int hbase = quarter * 2;
    atomicAdd(&g_z[(size_t)dn * NH + hbase],     s0);
    atomicAdd(&g_z[(size_t)dn * NH + hbase + 1], s1);
}

// ================= node kernel: 64 nodes x 128 cols x 3 matrices, full-B WMMA =================
#define NSM_AH   0
#define NSM_AL   (NSM_AH + 64 * AFULL * 2)    // 17408 each
#define NSM_BH   (NSM_AL + 64 * AFULL * 2)    // full 128 x BLD hi: 34816
#define NSM_BL   (NSM_BH + KDIM * BLD * 2)    // 34816
#define NSM_TOTAL (NSM_BL + KDIM * BLD * 2)   // 104448
// proj aliases the B region (69632 >= 33792), dead between matrices

__global__ __launch_bounds__(256, 2) void node_proj_qkv_kernel(
    const float* __restrict__ h,
    const float* __restrict__ Qb, const float* __restrict__ Kb, const float* __restrict__ Vb,
    float* __restrict__ outQ, float* __restrict__ outK, float* __restrict__ outV)
{
    extern __shared__ char smem[];
    __nv_bfloat16* sAH = reinterpret_cast<__nv_bfloat16*>(smem + NSM_AH);
    __nv_bfloat16* sAL = reinterpret_cast<__nv_bfloat16*>(smem + NSM_AL);
    __nv_bfloat16* sBH = reinterpret_cast<__nv_bfloat16*>(smem + NSM_BH);
    __nv_bfloat16* sBL = reinterpret_cast<__nv_bfloat16*>(smem + NSM_BL);
    float*        proj = reinterpret_cast<float*>(smem + NSM_BH);   // alias B region

    const int tid = threadIdx.x;
    const int wid = tid >> 5;
    const int r0  = blockIdx.x * 64;

    // convert full A (h rows) once: 64 x 128
    for (int i = tid; i < 64 * 32; i += 256) {
        int row = i >> 5, kq = i & 31;
        float4 v = make_float4(0.f, 0.f, 0.f, 0.f);
        if (r0 + row < NN)
            v = reinterpret_cast<const float4*>(h + (size_t)(r0 + row) * KDIM)[kq];
        const float a[4] = {v.x, v.y, v.z, v.w};
        int off = row * AFULL + kq * 4;
#pragma unroll
        for (int j = 0; j < 4; ++j) {
            __nv_bfloat16 hh, ll;
            cvt_split(a[j], hh, ll);
            sAH[off + j] = hh; sAL[off + j] = ll;
        }
    }

    const float* Bs[3] = {Qb, Kb, Vb};
    float* Os[3] = {outQ, outK, outV};
    const int widx[3] = {2, 3, 4};

    const int warp_m = wid & 1;
    const int warp_n = wid >> 1;

    for (int m = 0; m < 3; ++m) {
        __syncthreads();   // A ready (m=0) / prior proj reads done (m>0)
        // bulk copy of full hi/lo weight matrix (L2-resident)
        for (int i = tid; i < KDIM * (CD / 8); i += 256) {   // 2048 -> 8 iters
            int krow = i >> 4, q = i & 15;
            size_t goff = (size_t)krow * CD + q * 8;
            int soff = krow * BLD + q * 8;
            *reinterpret_cast<uint4*>(sBH + soff) = *reinterpret_cast<const uint4*>(&g_WH[widx[m]][goff]);
            *reinterpret_cast<uint4*>(sBL + soff) = *reinterpret_cast<const uint4*>(&g_WL[widx[m]][goff]);
        }
        __syncthreads();

        wmma::fragment<wmma::accumulator, 16, 16, 16, float> acc[2][2];
#pragma unroll
        for (int tm = 0; tm < 2; ++tm)
#pragma unroll
            for (int tn = 0; tn < 2; ++tn) wmma::fill_fragment(acc[tm][tn], 0.0f);

#pragma unroll
        for (int ks = 0; ks < KDIM / 16; ++ks) {
            wmma::fragment<wmma::matrix_a, 16, 16, 16, __nv_bfloat16, wmma::row_major> aH[2], aL[2];
            wmma::fragment<wmma::matrix_b, 16, 16, 16, __nv_bfloat16, wmma::row_major> bH[2], bL[2];
#pragma unroll
            for (int tm = 0; tm < 2; ++tm) {
                const int ar = warp_m * 32 + tm * 16;
                wmma::load_matrix_sync(aH[tm], sAH + ar * AFULL + ks * 16, AFULL);
                wmma::load_matrix_sync(aL[tm], sAL + ar * AFULL + ks * 16, AFULL);
            }
#pragma unroll
            for (int tn = 0; tn < 2; ++tn) {
                const int bc = warp_n * 32 + tn * 16;
                wmma::load_matrix_sync(bH[tn], sBH + ks * 16 * BLD + bc, BLD);
                wmma::load_matrix_sync(bL[tn], sBL + ks * 16 * BLD + bc, BLD);
            }
#pragma unroll
            for (int tm = 0; tm < 2; ++tm)
#pragma unroll
                for (int tn = 0; tn < 2; ++tn) {
                    wmma::mma_sync(acc[tm][tn], aH[tm], bH[tn], acc[tm][tn]);
                    wmma::mma_sync(acc[tm][tn], aH[tm], bL[tn], acc[tm][tn]);
                    wmma::mma_sync(acc[tm][tn], aL[tm], bH[tn], acc[tm][tn]);
                }
        }

        __syncthreads();   // MMAs done reading B before proj overwrites it
#pragma unroll
        for (int tm = 0; tm < 2; ++tm)
#pragma unroll
            for (int tn = 0; tn < 2; ++tn)
                wmma::store_matrix_sync(proj + (warp_m * 32 + tm * 16) * PLD + warp_n * 32 + tn * 16,
                                        acc[tm][tn], PLD, wmma::mem_row_major);
        __syncthreads();

        const int row = tid >> 2;
        const int cq  = (tid & 3) * 32;
        if (r0 + row < NN) {
            float* out = Os[m] + (size_t)(r0 + row) * CD + cq;
#pragma unroll
            for (int q = 0; q < 8; ++q) {
                float4 v  = *reinterpret_cast<const float4*>(proj + row * PLD + cq + q * 4);
                float4 bv = *reinterpret_cast<const float4*>(Bs[m] + cq + q * 4);
                reinterpret_cast<float4*>(out + q * 4)[0] =
                    make_float4(v.x + bv.x, v.y + bv.y, v.z + bv.z, v.w + bv.w);
            }
        }
    }
}

// ---------------- finalize: h_out = wV / (z + 1e-6) ----------------
__global__ __launch_bounds__(256) void finalize_kernel(float* __restrict__ out_h)
{
    int i = blockIdx.x * 256 + threadIdx.x;
    const int total = NN * CD / 4;
    if (i >= total) return;
    int n  = i >> 5;
    int cg = i & 31;
    int head = cg >> 2;
    float z = g_z[(size_t)n * NH + head] + 1e-6f;
    float inv = 1.0f / z;
    float4 v = reinterpret_cast<float4*>(out_h)[i];
    v.x *= inv; v.y *= inv; v.z *= inv; v.w *= inv;
    reinterpret_cast<float4*>(out_h)[i] = v;
}

// ---------------- launch ----------------
extern "C" void kernel_launch(void* const* d_in, const int* in_sizes, int n_in,
                              void* d_out, int out_size)
{
    const float* h   = (const float*)d_in[0];
    const float* e   = (const float*)d_in[1];
    const float* kr  = (const float*)d_in[2];
    const int*   src = (const int*)  d_in[3];
    const int*   dst = (const int*)  d_in[4];
    const float* Qw  = (const float*)d_in[5];
    const float* Qb  = (const float*)d_in[6];
    const float* Kw  = (const float*)d_in[7];
    const float* Kb  = (const float*)d_in[8];
    const float* Vw  = (const float*)d_in[9];
    const float* Vb  = (const float*)d_in[10];
    const float* Ew  = (const float*)d_in[11];
    const float* Eb  = (const float*)d_in[12];
    const float* Rw  = (const float*)d_in[13];
    const float* Rb  = (const float*)d_in[14];

    float* out_h = (float*)d_out;
    float* out_e = (float*)d_out + (size_t)NN * CD;

    cudaFuncSetAttribute(node_proj_qkv_kernel, cudaFuncAttributeMaxDynamicSharedMemorySize, NSM_TOTAL);
    cudaFuncSetAttribute(edge_kernel,          cudaFuncAttributeMaxDynamicSharedMemorySize, ESM_TOTAL);

    cudaMemsetAsync(out_h, 0, (size_t)NN * CD * sizeof(float));
    void* zp = nullptr;
    cudaGetSymbolAddress(&zp, g_z);
    cudaMemsetAsync(zp, 0, (size_t)NN * NH * sizeof(float));

    void *qp, *kp, *vp;
    cudaGetSymbolAddress(&qp, g_Qh);
    cudaGetSymbolAddress(&kp, g_Kh);
    cudaGetSymbolAddress(&vp, g_Vh);

    convert_weights_kernel<<<(KDIM * CD + 255) / 256, 256>>>(Ew, Rw, Qw, Kw, Vw);

    const int nodeBlocks = (NN + 63) / 64;  // 782
    node_proj_qkv_kernel<<<nodeBlocks, 256, NSM_TOTAL>>>(
        h, Qb, Kb, Vb, (float*)qp, (float*)kp, (float*)vp);

    edge_kernel<<<EE / BM, 256, ESM_TOTAL>>>(e, kr, src, dst, Eb, Rb, out_h, out_e);

    const int finBlocks = (NN * CD / 4 + 255) / 256;
    finalize_kernel<<<finBlocks, 256>>>(out_h);
}

// round 9
// speedup vs baseline: 3.1996x; 1.2515x over previous
#include <cuda_runtime.h>
#include <cuda_bf16.h>
#include <cuda_fp16.h>
#include <mma.h>
#include <math.h>
#include <stdint.h>

using namespace nvcuda;

#define NN 50000
#define EE 800000
#define KDIM 128
#define CD 128
#define NH 8

#define BM 64        // edges per block (edge kernel)
#define CHK 32       // K chunk
#define ALD 40       // A smem leading dim (half)
#define AFULL 136    // A smem leading dim full-K (bf16, node)
#define BLD 136      // B smem leading dim (16-bit elems)
#define PLD 132      // proj smem leading dim (floats)

// ---------------- device scratch ----------------
__device__ float g_Qh[(size_t)NN * CD];
__device__ float g_Kh[(size_t)NN * CD];
__device__ float g_Vh[(size_t)NN * CD];
__device__ float g_z[(size_t)NN * NH];
// edge weights: fp16 hi/lo 2-split (0=Ew 1=Rw)
__device__ __align__(16) __half g_We_h[2][KDIM * CD];
__device__ __align__(16) __half g_We_l[2][KDIM * CD];
// node weights: bf16 hi/lo (0=Qw 1=Kw 2=Vw)
__device__ __align__(16) __nv_bfloat16 g_Wn_h[3][KDIM * CD];
__device__ __align__(16) __nv_bfloat16 g_Wn_l[3][KDIM * CD];

__device__ __forceinline__ void red_add_v4(float* p, float a, float b, float c, float d) {
    asm volatile("red.global.add.v4.f32 [%0], {%1, %2, %3, %4};"
                 :: "l"(p), "f"(a), "f"(b), "f"(c), "f"(d) : "memory");
}
__device__ __forceinline__ void cvt_split_bf(float x, __nv_bfloat16& hi, __nv_bfloat16& lo) {
    hi = __float2bfloat16(x);
    lo = __float2bfloat16(x - __bfloat162float(hi));
}
__device__ __forceinline__ void cvt_split_h(float x, __half& hi, __half& lo) {
    hi = __float2half_rn(x);
    lo = __float2half_rn(x - __half2float(hi));
}

// ---------------- weight conversion (once per launch) ----------------
__global__ __launch_bounds__(256) void convert_weights_kernel(
    const float* __restrict__ Ew, const float* __restrict__ Rw,
    const float* __restrict__ Qw, const float* __restrict__ Kw,
    const float* __restrict__ Vw)
{
    int i = blockIdx.x * 256 + threadIdx.x;
    if (i >= KDIM * CD) return;
    {
        __half h, l;
        cvt_split_h(Ew[i], h, l); g_We_h[0][i] = h; g_We_l[0][i] = l;
        cvt_split_h(Rw[i], h, l); g_We_h[1][i] = h; g_We_l[1][i] = l;
    }
    {
        __nv_bfloat16 h, l;
        cvt_split_bf(Qw[i], h, l); g_Wn_h[0][i] = h; g_Wn_l[0][i] = l;
        cvt_split_bf(Kw[i], h, l); g_Wn_h[1][i] = h; g_Wn_l[1][i] = l;
        cvt_split_bf(Vw[i], h, l); g_Wn_h[2][i] = h; g_Wn_l[2][i] = l;
    }
}

// ================= edge kernel: 64 edges x 128 cols, fp16 A1xB2 =================
#define ESM_SIDX  0                          // 512
#define ESM_AE    512                        // 64*40*2 = 5120
#define ESM_AK    (ESM_AE + BM * ALD * 2)
#define ESM_BEH   (ESM_AK + BM * ALD * 2)    // 32*136*2 = 8704 each
#define ESM_BEL   (ESM_BEH + CHK * BLD * 2)
#define ESM_BRH   (ESM_BEL + CHK * BLD * 2)
#define ESM_BRL   (ESM_BRH + CHK * BLD * 2)
#define ESM_PROJ  (ESM_BRL + CHK * BLD * 2)
#define ESM_TOTAL (ESM_PROJ + BM * PLD * 4)  // 79360
// projE aliases the 34816-byte B region (needs 33792), dead after last MMA

__global__ __launch_bounds__(256, 2) void edge_kernel(
    const float* __restrict__ e,
    const float* __restrict__ kr,
    const int*  __restrict__ src,
    const int*  __restrict__ dst,
    const float* __restrict__ Eb,
    const float* __restrict__ Rb,
    float* __restrict__ out_h,
    float* __restrict__ out_e)
{
    extern __shared__ char smem[];
    int*    sidx = reinterpret_cast<int*>(smem + ESM_SIDX);
    __half* sAE  = reinterpret_cast<__half*>(smem + ESM_AE);
    __half* sAK  = reinterpret_cast<__half*>(smem + ESM_AK);
    __half* sBEh = reinterpret_cast<__half*>(smem + ESM_BEH);
    __half* sBEl = reinterpret_cast<__half*>(smem + ESM_BEL);
    __half* sBRh = reinterpret_cast<__half*>(smem + ESM_BRH);
    __half* sBRl = reinterpret_cast<__half*>(smem + ESM_BRL);
    float*  projR = reinterpret_cast<float*>(smem + ESM_PROJ);
    float*  projE = reinterpret_cast<float*>(smem + ESM_BEH);   // alias, post-MMA

    const int tid = threadIdx.x;
    const int wid = tid >> 5;
    const int r0  = blockIdx.x * BM;

    if (tid < BM) {
        sidx[tid]      = src[r0 + tid];
        sidx[BM + tid] = dst[r0 + tid];
    }

    const int warp_m = wid & 1;    // 2 x 32 edges
    const int warp_n = wid >> 1;   // 4 x 32 cols

    const int arow0 = tid >> 3;    // 0..31
    const int aq    = tid & 7;     // float4 index in k-chunk

    wmma::fragment<wmma::accumulator, 16, 16, 16, float> accE[2][2], accR[2][2];
#pragma unroll
    for (int tm = 0; tm < 2; ++tm)
#pragma unroll
        for (int tn = 0; tn < 2; ++tn) {
            wmma::fill_fragment(accE[tm][tn], 0.0f);
            wmma::fill_fragment(accR[tm][tn], 0.0f);
        }

    // prologue: prefetch chunk 0 e/kr to registers
    float4 pve[2], pvk[2];
#pragma unroll
    for (int it = 0; it < 2; ++it) {
        const int row = arow0 + 32 * it;
        pve[it] = *reinterpret_cast<const float4*>(e  + (size_t)(r0 + row) * KDIM + aq * 4);
        pvk[it] = *reinterpret_cast<const float4*>(kr + (size_t)(r0 + row) * KDIM + aq * 4);
    }

    for (int ch = 0; ch < KDIM / CHK; ++ch) {
        if (ch > 0) __syncthreads();
        // ---- A regs -> single fp16 smem ----
#pragma unroll
        for (int it = 0; it < 2; ++it) {
            const int row = arow0 + 32 * it;
            const int off = row * ALD + aq * 4;
            __half2* pe2 = reinterpret_cast<__half2*>(sAE + off);
            __half2* pk2 = reinterpret_cast<__half2*>(sAK + off);
            pe2[0] = __halves2half2(__float2half_rn(pve[it].x), __float2half_rn(pve[it].y));
            pe2[1] = __halves2half2(__float2half_rn(pve[it].z), __float2half_rn(pve[it].w));
            pk2[0] = __halves2half2(__float2half_rn(pvk[it].x), __float2half_rn(pvk[it].y));
            pk2[1] = __halves2half2(__float2half_rn(pvk[it].z), __float2half_rn(pvk[it].w));
        }
        // ---- copy precomputed fp16 hi/lo B chunk (L2-resident) ----
#pragma unroll
        for (int i = tid; i < CHK * (CD / 8); i += 256) {   // 512 -> 2 iters
            int krow = i >> 4, q = i & 15;
            size_t goff = (size_t)(ch * CHK + krow) * CD + q * 8;
            int soff = krow * BLD + q * 8;
            *reinterpret_cast<uint4*>(sBEh + soff) = *reinterpret_cast<const uint4*>(&g_We_h[0][goff]);
            *reinterpret_cast<uint4*>(sBEl + soff) = *reinterpret_cast<const uint4*>(&g_We_l[0][goff]);
            *reinterpret_cast<uint4*>(sBRh + soff) = *reinterpret_cast<const uint4*>(&g_We_h[1][goff]);
            *reinterpret_cast<uint4*>(sBRl + soff) = *reinterpret_cast<const uint4*>(&g_We_l[1][goff]);
        }
        __syncthreads();

        // prefetch NEXT chunk's A while MMAs run
        if (ch < KDIM / CHK - 1) {
            const int gk = (ch + 1) * CHK + aq * 4;
#pragma unroll
            for (int it = 0; it < 2; ++it) {
                const int row = arow0 + 32 * it;
                pve[it] = *reinterpret_cast<const float4*>(e  + (size_t)(r0 + row) * KDIM + gk);
                pvk[it] = *reinterpret_cast<const float4*>(kr + (size_t)(r0 + row) * KDIM + gk);
            }
        }

#pragma unroll
        for (int ks = 0; ks < 2; ++ks) {
            wmma::fragment<wmma::matrix_a, 16, 16, 16, __half, wmma::row_major> a[2];
            wmma::fragment<wmma::matrix_b, 16, 16, 16, __half, wmma::row_major> bH[2], bL[2];
            // E
#pragma unroll
            for (int tm = 0; tm < 2; ++tm)
                wmma::load_matrix_sync(a[tm], sAE + (warp_m * 32 + tm * 16) * ALD + ks * 16, ALD);
#pragma unroll
            for (int tn = 0; tn < 2; ++tn) {
                const int bc = warp_n * 32 + tn * 16;
                wmma::load_matrix_sync(bH[tn], sBEh + ks * 16 * BLD + bc, BLD);
                wmma::load_matrix_sync(bL[tn], sBEl + ks * 16 * BLD + bc, BLD);
            }
#pragma unroll
            for (int tm = 0; tm < 2; ++tm)
#pragma unroll
                for (int tn = 0; tn < 2; ++tn) {
                    wmma::mma_sync(accE[tm][tn], a[tm], bH[tn], accE[tm][tn]);
                    wmma::mma_sync(accE[tm][tn], a[tm], bL[tn], accE[tm][tn]);
                }
            // R
#pragma unroll
            for (int tm = 0; tm < 2; ++tm)
                wmma::load_matrix_sync(a[tm], sAK + (warp_m * 32 + tm * 16) * ALD + ks * 16, ALD);
#pragma unroll
            for (int tn = 0; tn < 2; ++tn) {
                const int bc = warp_n * 32 + tn * 16;
                wmma::load_matrix_sync(bH[tn], sBRh + ks * 16 * BLD + bc, BLD);
                wmma::load_matrix_sync(bL[tn], sBRl + ks * 16 * BLD + bc, BLD);
            }
#pragma unroll
            for (int tm = 0; tm < 2; ++tm)
#pragma unroll
                for (int tn = 0; tn < 2; ++tn) {
                    wmma::mma_sync(accR[tm][tn], a[tm], bH[tn], accR[tm][tn]);
                    wmma::mma_sync(accR[tm][tn], a[tm], bL[tn], accR[tm][tn]);
                }
        }
    }

    // ---- epilogue: single staging pass ----
    __syncthreads();
#pragma unroll
    for (int tm = 0; tm < 2; ++tm)
#pragma unroll
        for (int tn = 0; tn < 2; ++tn) {
            const int po = (warp_m * 32 + tm * 16) * PLD + warp_n * 32 + tn * 16;
            wmma::store_matrix_sync(projR + po, accR[tm][tn], PLD, wmma::mem_row_major);
            wmma::store_matrix_sync(projE + po, accE[tm][tn], PLD, wmma::mem_row_major);
        }
    __syncthreads();

    const int erow    = tid & 63;
    const int quarter = tid >> 6;
    const int cc      = quarter * 32;

    const int gedge = r0 + erow;
    const int sn = sidx[erow];
    const int dn = sidx[BM + erow];

    float vv[32];
    float s0 = 0.f, s1 = 0.f;
    float* oe = out_e + (size_t)gedge * CD + cc;
#pragma unroll
    for (int q = 0; q < 8; ++q) {
        float4 rv  = *reinterpret_cast<const float4*>(projR + erow * PLD + cc + q * 4);
        float4 rbv = *reinterpret_cast<const float4*>(Rb + cc + q * 4);
        float4 ev  = *reinterpret_cast<const float4*>(projE + erow * PLD + cc + q * 4);
        float4 ebv = *reinterpret_cast<const float4*>(Eb + cc + q * 4);
        float4 kv  = *reinterpret_cast<const float4*>(g_Kh + (size_t)sn * CD + cc + q * 4);
        float4 qv  = *reinterpret_cast<const float4*>(g_Qh + (size_t)dn * CD + cc + q * 4);
        float4 v4  = *reinterpret_cast<const float4*>(g_Vh + (size_t)sn * CD + cc + q * 4);
        vv[q*4+0]=v4.x; vv[q*4+1]=v4.y; vv[q*4+2]=v4.z; vv[q*4+3]=v4.w;
        const float pr[4] = {rv.x + rbv.x, rv.y + rbv.y, rv.z + rbv.z, rv.w + rbv.w};
        const float pe[4] = {ev.x + ebv.x, ev.y + ebv.y, ev.z + ebv.z, ev.w + ebv.w};
        const float kk[4] = {kv.x, kv.y, kv.z, kv.w};
        const float qq[4] = {qv.x, qv.y, qv.z, qv.w};
        float sc[4];
#pragma unroll
        for (int j = 0; j < 4; ++j) {
            float t = fmaf(kk[j] * qq[j], 0.25f, pr[j]) * pe[j];
            sc[j] = t;
            if (q < 4) s0 += t; else s1 += t;
        }
        __stcs(reinterpret_cast<float4*>(oe + q * 4), make_float4(sc[0], sc[1], sc[2], sc[3]));
    }

    s0 = __expf(fminf(fmaxf(s0, -5.0f), 5.0f));
    s1 = __expf(fminf(fmaxf(s1, -5.0f), 5.0f));

    float* w = out_h + (size_t)dn * CD + cc;
#pragma unroll
    for (int q = 0; q < 8; ++q) {
        float s = (q < 4) ? s0 : s1;
        red_add_v4(w + q * 4, vv[q*4+0]*s, vv[q*4+1]*s, vv[q*4+2]*s, vv[q*4+3]*s);
    }
    const int hbase = quarter * 2;
    atomicAdd(&g_z[(size_t)dn * NH + hbase],     s0);
    atomicAdd(&g_z[(size_t)dn * NH + hbase + 1], s1);
}

// ================= node kernel: bf16 3-split (unchanged from R8) =================
#define NSM_AH   0
#define NSM_AL   (NSM_AH + 64 * AFULL * 2)
#define NSM_BH   (NSM_AL + 64 * AFULL * 2)
#define NSM_BL   (NSM_BH + KDIM * BLD * 2)
#define NSM_TOTAL (NSM_BL + KDIM * BLD * 2)   // 104448

__global__ __launch_bounds__(256, 2) void node_proj_qkv_kernel(
    const float* __restrict__ h,
    const float* __restrict__ Qb, const float* __restrict__ Kb, const float* __restrict__ Vb,
    float* __restrict__ outQ, float* __restrict__ outK, float* __restrict__ outV)
{
    extern __shared__ char smem[];
    __nv_bfloat16* sAH = reinterpret_cast<__nv_bfloat16*>(smem + NSM_AH);
    __nv_bfloat16* sAL = reinterpret_cast<__nv_bfloat16*>(smem + NSM_AL);
    __nv_bfloat16* sBH = reinterpret_cast<__nv_bfloat16*>(smem + NSM_BH);
    __nv_bfloat16* sBL = reinterpret_cast<__nv_bfloat16*>(smem + NSM_BL);
    float*        proj = reinterpret_cast<float*>(smem + NSM_BH);   // alias B region

    const int tid = threadIdx.x;
    const int wid = tid >> 5;
    const int r0  = blockIdx.x * 64;

    for (int i = tid; i < 64 * 32; i += 256) {
        int row = i >> 5, kq = i & 31;
        float4 v = make_float4(0.f, 0.f, 0.f, 0.f);
        if (r0 + row < NN)
            v = reinterpret_cast<const float4*>(h + (size_t)(r0 + row) * KDIM)[kq];
        const float a[4] = {v.x, v.y, v.z, v.w};
        int off = row * AFULL + kq * 4;
#pragma unroll
        for (int j = 0; j < 4; ++j) {
            __nv_bfloat16 hh, ll;
            cvt_split_bf(a[j], hh, ll);
            sAH[off + j] = hh; sAL[off + j] = ll;
        }
    }

    const float* Bs[3] = {Qb, Kb, Vb};
    float* Os[3] = {outQ, outK, outV};

    const int warp_m = wid & 1;
    const int warp_n = wid >> 1;

    for (int m = 0; m < 3; ++m) {
        __syncthreads();
        for (int i = tid; i < KDIM * (CD / 8); i += 256) {
            int krow = i >> 4, q = i & 15;
            size_t goff = (size_t)krow * CD + q * 8;
            int soff = krow * BLD + q * 8;
            *reinterpret_cast<uint4*>(sBH + soff) = *reinterpret_cast<const uint4*>(&g_Wn_h[m][goff]);
            *reinterpret_cast<uint4*>(sBL + soff) = *reinterpret_cast<const uint4*>(&g_Wn_l[m][goff]);
        }
        __syncthreads();

        wmma::fragment<wmma::accumulator, 16, 16, 16, float> acc[2][2];
#pragma unroll
        for (int tm = 0; tm < 2; ++tm)
#pragma unroll
            for (int tn = 0; tn < 2; ++tn) wmma::fill_fragment(acc[tm][tn], 0.0f);

#pragma unroll
        for (int ks = 0; ks < KDIM / 16; ++ks) {
            wmma::fragment<wmma::matrix_a, 16, 16, 16, __nv_bfloat16, wmma::row_major> aH[2], aL[2];
            wmma::fragment<wmma::matrix_b, 16, 16, 16, __nv_bfloat16, wmma::row_major> bH[2], bL[2];
#pragma unroll
            for (int tm = 0; tm < 2; ++tm) {
                const int ar = warp_m * 32 + tm * 16;
                wmma::load_matrix_sync(aH[tm], sAH + ar * AFULL + ks * 16, AFULL);
                wmma::load_matrix_sync(aL[tm], sAL + ar * AFULL + ks * 16, AFULL);
            }
#pragma unroll
            for (int tn = 0; tn < 2; ++tn) {
                const int bc = warp_n * 32 + tn * 16;
                wmma::load_matrix_sync(bH[tn], sBH + ks * 16 * BLD + bc, BLD);
                wmma::load_matrix_sync(bL[tn], sBL + ks * 16 * BLD + bc, BLD);
            }
#pragma unroll
            for (int tm = 0; tm < 2; ++tm)
#pragma unroll
                for (int tn = 0; tn < 2; ++tn) {
                    wmma::mma_sync(acc[tm][tn], aH[tm], bH[tn], acc[tm][tn]);
                    wmma::mma_sync(acc[tm][tn], aH[tm], bL[tn], acc[tm][tn]);
                    wmma::mma_sync(acc[tm][tn], aL[tm], bH[tn], acc[tm][tn]);
                }
        }

        __syncthreads();
#pragma unroll
        for (int tm = 0; tm < 2; ++tm)
#pragma unroll
            for (int tn = 0; tn < 2; ++tn)
                wmma::store_matrix_sync(proj + (warp_m * 32 + tm * 16) * PLD + warp_n * 32 + tn * 16,
                                        acc[tm][tn], PLD, wmma::mem_row_major);
        __syncthreads();

        const int row = tid >> 2;
        const int cq  = (tid & 3) * 32;
        if (r0 + row < NN) {
            float* out = Os[m] + (size_t)(r0 + row) * CD + cq;
#pragma unroll
            for (int q = 0; q < 8; ++q) {
                float4 v  = *reinterpret_cast<const float4*>(proj + row * PLD + cq + q * 4);
                float4 bv = *reinterpret_cast<const float4*>(Bs[m] + cq + q * 4);
                reinterpret_cast<float4*>(out + q * 4)[0] =
                    make_float4(v.x + bv.x, v.y + bv.y, v.z + bv.z, v.w + bv.w);
            }
        }
    }
}

// ---------------- finalize ----------------
__global__ __launch_bounds__(256) void finalize_kernel(float* __restrict__ out_h)
{
    int i = blockIdx.x * 256 + threadIdx.x;
    const int total = NN * CD / 4;
    if (i >= total) return;
    int n  = i >> 5;
    int cg = i & 31;
    int head = cg >> 2;
    float z = g_z[(size_t)n * NH + head] + 1e-6f;
    float inv = 1.0f / z;
    float4 v = reinterpret_cast<float4*>(out_h)[i];
    v.x *= inv; v.y *= inv; v.z *= inv; v.w *= inv;
    reinterpret_cast<float4*>(out_h)[i] = v;
}

// ---------------- launch ----------------
extern "C" void kernel_launch(void* const* d_in, const int* in_sizes, int n_in,
                              void* d_out, int out_size)
{
    const float* h   = (const float*)d_in[0];
    const float* e   = (const float*)d_in[1];
    const float* kr  = (const float*)d_in[2];
    const int*   src = (const int*)  d_in[3];
    const int*   dst = (const int*)  d_in[4];
    const float* Qw  = (const float*)d_in[5];
    const float* Qb  = (const float*)d_in[6];
    const float* Kw  = (const float*)d_in[7];
    const float* Kb  = (const float*)d_in[8];
    const float* Vw  = (const float*)d_in[9];
    const float* Vb  = (const float*)d_in[10];
    const float* Ew  = (const float*)d_in[11];
    const float* Eb  = (const float*)d_in[12];
    const float* Rw  = (const float*)d_in[13];
    const float* Rb  = (const float*)d_in[14];

    float* out_h = (float*)d_out;
    float* out_e = (float*)d_out + (size_t)NN * CD;

    cudaFuncSetAttribute(node_proj_qkv_kernel, cudaFuncAttributeMaxDynamicSharedMemorySize, NSM_TOTAL);
    cudaFuncSetAttribute(edge_kernel,          cudaFuncAttributeMaxDynamicSharedMemorySize, ESM_TOTAL);

    cudaMemsetAsync(out_h, 0, (size_t)NN * CD * sizeof(float));
    void* zp = nullptr;
    cudaGetSymbolAddress(&zp, g_z);
    cudaMemsetAsync(zp, 0, (size_t)NN * NH * sizeof(float));

    void *qp, *kp, *vp;
    cudaGetSymbolAddress(&qp, g_Qh);
    cudaGetSymbolAddress(&kp, g_Kh);
    cudaGetSymbolAddress(&vp, g_Vh);

    convert_weights_kernel<<<(KDIM * CD + 255) / 256, 256>>>(Ew, Rw, Qw, Kw, Vw);

    const int nodeBlocks = (NN + 63) / 64;  // 782
    node_proj_qkv_kernel<<<nodeBlocks, 256, NSM_TOTAL>>>(
        h, Qb, Kb, Vb, (float*)qp, (float*)kp, (float*)vp);

    edge_kernel<<<EE / BM, 256, ESM_TOTAL>>>(e, kr, src, dst, Eb, Rb, out_h, out_e);

    const int finBlocks = (NN * CD / 4 + 255) / 256;
    finalize_kernel<<<finBlocks, 256>>>(out_h);
}

// round 10
// speedup vs baseline: 3.2861x; 1.0270x over previous
#include <cuda_runtime.h>
#include <cuda_bf16.h>
#include <cuda_fp16.h>
#include <mma.h>
#include <math.h>
#include <stdint.h>

using namespace nvcuda;

#define NN 50000
#define EE 800000
#define KDIM 128
#define CD 128
#define NH 8

#define BM 64        // edges per block (edge kernel)
#define CHK 32       // K chunk
#define KCH (KDIM / CHK)
#define ALD 40       // A smem leading dim (half)
#define AFULL 136    // A smem leading dim full-K (bf16, node)
#define BLD 136      // B smem leading dim (16-bit elems)
#define PLD 132      // proj smem leading dim (floats)

// ---------------- device scratch ----------------
__device__ float g_Qh[(size_t)NN * CD];
__device__ float g_Kh[(size_t)NN * CD];
__device__ float g_Vh[(size_t)NN * CD];
__device__ float g_z[(size_t)NN * NH];
// edge weights: fp16 hi/lo 2-split (0=Ew 1=Rw)
__device__ __align__(16) __half g_We_h[2][KDIM * CD];
__device__ __align__(16) __half g_We_l[2][KDIM * CD];
// node weights: bf16 hi/lo (0=Qw 1=Kw 2=Vw)
__device__ __align__(16) __nv_bfloat16 g_Wn_h[3][KDIM * CD];
__device__ __align__(16) __nv_bfloat16 g_Wn_l[3][KDIM * CD];

__device__ __forceinline__ void red_add_v4(float* p, float a, float b, float c, float d) {
    asm volatile("red.global.add.v4.f32 [%0], {%1, %2, %3, %4};"
                 :: "l"(p), "f"(a), "f"(b), "f"(c), "f"(d) : "memory");
}
__device__ __forceinline__ void cvt_split_bf(float x, __nv_bfloat16& hi, __nv_bfloat16& lo) {
    hi = __float2bfloat16(x);
    lo = __float2bfloat16(x - __bfloat162float(hi));
}
__device__ __forceinline__ void cvt_split_h(float x, __half& hi, __half& lo) {
    hi = __float2half_rn(x);
    lo = __float2half_rn(x - __half2float(hi));
}
__device__ __forceinline__ void cp16(uint32_t saddr, const void* gptr) {
    asm volatile("cp.async.cg.shared.global [%0], [%1], 16;"
                 :: "r"(saddr), "l"(gptr) : "memory");
}
__device__ __forceinline__ void cp_commit() {
    asm volatile("cp.async.commit_group;" ::: "memory");
}
__device__ __forceinline__ void cp_wait_all() {
    asm volatile("cp.async.wait_group 0;" ::: "memory");
}

// ---------------- weight conversion (once per launch) ----------------
__global__ __launch_bounds__(256) void convert_weights_kernel(
    const float* __restrict__ Ew, const float* __restrict__ Rw,
    const float* __restrict__ Qw, const float* __restrict__ Kw,
    const float* __restrict__ Vw)
{
    int i = blockIdx.x * 256 + threadIdx.x;
    if (i >= KDIM * CD) return;
    {
        __half h, l;
        cvt_split_h(Ew[i], h, l); g_We_h[0][i] = h; g_We_l[0][i] = l;
        cvt_split_h(Rw[i], h, l); g_We_h[1][i] = h; g_We_l[1][i] = l;
    }
    {
        __nv_bfloat16 h, l;
        cvt_split_bf(Qw[i], h, l); g_Wn_h[0][i] = h; g_Wn_l[0][i] = l;
        cvt_split_bf(Kw[i], h, l); g_Wn_h[1][i] = h; g_Wn_l[1][i] = l;
        cvt_split_bf(Vw[i], h, l); g_Wn_h[2][i] = h; g_Wn_l[2][i] = l;
    }
}

// ================= edge kernel: double-buffered pipeline, fp16 A1xB2 =================
#define ESM_SIDX  0                           // 512
#define ESM_A     512                         // 2 bufs x (AE 5120 + AK 5120) = 20480
#define ABUF_SZ   (2 * BM * ALD * 2)          // 10240 bytes per buffer
#define ESM_B     (ESM_A + 2 * ABUF_SZ)       // 20992
#define SBT       (CHK * BLD * 2)             // 8704 bytes per sub-tile
#define BBUF_SZ   (4 * SBT)                   // 34816 (BEh,BEl,BRh,BRl)
#define ESM_TOTAL (ESM_B + 2 * BBUF_SZ)       // 90624
// epilogue staging: projR aliases B buf0 (34816 >= 33792), projE aliases B buf1

__global__ __launch_bounds__(256, 2) void edge_kernel(
    const float* __restrict__ e,
    const float* __restrict__ kr,
    const int*  __restrict__ src,
    const int*  __restrict__ dst,
    const float* __restrict__ Eb,
    const float* __restrict__ Rb,
    float* __restrict__ out_h,
    float* __restrict__ out_e)
{
    extern __shared__ char smem[];
    int*   sidx = reinterpret_cast<int*>(smem + ESM_SIDX);
    float* projR = reinterpret_cast<float*>(smem + ESM_B);             // alias B buf0
    float* projE = reinterpret_cast<float*>(smem + ESM_B + BBUF_SZ);   // alias B buf1

    const int tid = threadIdx.x;
    const int wid = tid >> 5;
    const int r0  = blockIdx.x * BM;

    // B-copy index mapping: 2 iterations of (krow, q)
    const int bkrow0 = tid >> 4;          // 0..15
    const int bq     = tid & 15;          // uint4 col group

    // ---- issue B(0) cp.async immediately ----
    {
        uint32_t bdst = (uint32_t)__cvta_generic_to_shared(smem + ESM_B);
#pragma unroll
        for (int it = 0; it < 2; ++it) {
            int krow = bkrow0 + 16 * it;
            size_t goff = (size_t)krow * CD + bq * 8;
            uint32_t soff = (uint32_t)(krow * BLD + bq * 8) * 2;
            cp16(bdst + 0 * SBT + soff, &g_We_h[0][goff]);
            cp16(bdst + 1 * SBT + soff, &g_We_l[0][goff]);
            cp16(bdst + 2 * SBT + soff, &g_We_h[1][goff]);
            cp16(bdst + 3 * SBT + soff, &g_We_l[1][goff]);
        }
        cp_commit();
    }

    if (tid < BM) {
        sidx[tid]      = src[r0 + tid];
        sidx[BM + tid] = dst[r0 + tid];
    }

    const int warp_m = wid & 1;    // 2 x 32 edges
    const int warp_n = wid >> 1;   // 4 x 32 cols

    const int arow0 = tid >> 3;    // 0..31
    const int aq    = tid & 7;     // float4 index in k-chunk

    wmma::fragment<wmma::accumulator, 16, 16, 16, float> accE[2][2], accR[2][2];
#pragma unroll
    for (int tm = 0; tm < 2; ++tm)
#pragma unroll
        for (int tn = 0; tn < 2; ++tn) {
            wmma::fill_fragment(accE[tm][tn], 0.0f);
            wmma::fill_fragment(accR[tm][tn], 0.0f);
        }

    // prologue: prefetch chunk 0 e/kr to registers
    float4 pve[2], pvk[2];
#pragma unroll
    for (int it = 0; it < 2; ++it) {
        const int row = arow0 + 32 * it;
        pve[it] = *reinterpret_cast<const float4*>(e  + (size_t)(r0 + row) * KDIM + aq * 4);
        pvk[it] = *reinterpret_cast<const float4*>(kr + (size_t)(r0 + row) * KDIM + aq * 4);
    }

    for (int ch = 0; ch < KCH; ++ch) {
        const int ab = ch & 1;
        __half* sAE = reinterpret_cast<__half*>(smem + ESM_A + ab * ABUF_SZ);
        __half* sAK = sAE + BM * ALD;

        // ---- STS A(ch) from prefetched regs (fp16 single) ----
#pragma unroll
        for (int it = 0; it < 2; ++it) {
            const int row = arow0 + 32 * it;
            const int off = row * ALD + aq * 4;
            __half2* pe2 = reinterpret_cast<__half2*>(sAE + off);
            __half2* pk2 = reinterpret_cast<__half2*>(sAK + off);
            pe2[0] = __halves2half2(__float2half_rn(pve[it].x), __float2half_rn(pve[it].y));
            pe2[1] = __halves2half2(__float2half_rn(pve[it].z), __float2half_rn(pve[it].w));
            pk2[0] = __halves2half2(__float2half_rn(pvk[it].x), __float2half_rn(pvk[it].y));
            pk2[1] = __halves2half2(__float2half_rn(pvk[it].z), __float2half_rn(pvk[it].w));
        }
        // ---- prefetch A(ch+1) regs ----
        if (ch < KCH - 1) {
            const int gk = (ch + 1) * CHK + aq * 4;
#pragma unroll
            for (int it = 0; it < 2; ++it) {
                const int row = arow0 + 32 * it;
                pve[it] = *reinterpret_cast<const float4*>(e  + (size_t)(r0 + row) * KDIM + gk);
                pvk[it] = *reinterpret_cast<const float4*>(kr + (size_t)(r0 + row) * KDIM + gk);
            }
        }

        // ---- B(ch) complete + A STS visible ----
        cp_wait_all();
        __syncthreads();

        // ---- issue B(ch+1) (overlaps this chunk's MMAs; target buffer's
        //      prior readers finished before the sync above) ----
        if (ch < KCH - 1) {
            uint32_t bdst = (uint32_t)__cvta_generic_to_shared(
                smem + ESM_B + ((ch + 1) & 1) * BBUF_SZ);
#pragma unroll
            for (int it = 0; it < 2; ++it) {
                int krow = bkrow0 + 16 * it;
                size_t goff = (size_t)((ch + 1) * CHK + krow) * CD + bq * 8;
                uint32_t soff = (uint32_t)(krow * BLD + bq * 8) * 2;
                cp16(bdst + 0 * SBT + soff, &g_We_h[0][goff]);
                cp16(bdst + 1 * SBT + soff, &g_We_l[0][goff]);
                cp16(bdst + 2 * SBT + soff, &g_We_h[1][goff]);
                cp16(bdst + 3 * SBT + soff, &g_We_l[1][goff]);
            }
            cp_commit();
        }

        __half* sB   = reinterpret_cast<__half*>(smem + ESM_B + ab * BBUF_SZ);
        __half* sBEh = sB;
        __half* sBEl = sB + SBT / 2;
        __half* sBRh = sB + SBT;
        __half* sBRl = sB + 3 * (SBT / 2);

        // ---- MMAs ----
#pragma unroll
        for (int ks = 0; ks < 2; ++ks) {
            wmma::fragment<wmma::matrix_a, 16, 16, 16, __half, wmma::row_major> a[2];
            wmma::fragment<wmma::matrix_b, 16, 16, 16, __half, wmma::row_major> bH[2], bL[2];
            // E
#pragma unroll
            for (int tm = 0; tm < 2; ++tm)
                wmma::load_matrix_sync(a[tm], sAE + (warp_m * 32 + tm * 16) * ALD + ks * 16, ALD);
#pragma unroll
            for (int tn = 0; tn < 2; ++tn) {
                const int bc = warp_n * 32 + tn * 16;
                wmma::load_matrix_sync(bH[tn], sBEh + ks * 16 * BLD + bc, BLD);
                wmma::load_matrix_sync(bL[tn], sBEl + ks * 16 * BLD + bc, BLD);
            }
#pragma unroll
            for (int tm = 0; tm < 2; ++tm)
#pragma unroll
                for (int tn = 0; tn < 2; ++tn) {
                    wmma::mma_sync(accE[tm][tn], a[tm], bH[tn], accE[tm][tn]);
                    wmma::mma_sync(accE[tm][tn], a[tm], bL[tn], accE[tm][tn]);
                }
            // R
#pragma unroll
            for (int tm = 0; tm < 2; ++tm)
                wmma::load_matrix_sync(a[tm], sAK + (warp_m * 32 + tm * 16) * ALD + ks * 16, ALD);
#pragma unroll
            for (int tn = 0; tn < 2; ++tn) {
                const int bc = warp_n * 32 + tn * 16;
                wmma::load_matrix_sync(bH[tn], sBRh + ks * 16 * BLD + bc, BLD);
                wmma::load_matrix_sync(bL[tn], sBRl + ks * 16 * BLD + bc, BLD);
            }
#pragma unroll
            for (int tm = 0; tm < 2; ++tm)
#pragma unroll
                for (int tn = 0; tn < 2; ++tn) {
                    wmma::mma_sync(accR[tm][tn], a[tm], bH[tn], accR[tm][tn]);
                    wmma::mma_sync(accR[tm][tn], a[tm], bL[tn], accR[tm][tn]);
                }
        }
    }

    // ---- epilogue: stage both projections into dead B buffers ----
    __syncthreads();
#pragma unroll
    for (int tm = 0; tm < 2; ++tm)
#pragma unroll
        for (int tn = 0; tn < 2; ++tn) {
            const int po = (warp_m * 32 + tm * 16) * PLD + warp_n * 32 + tn * 16;
            wmma::store_matrix_sync(projR + po, accR[tm][tn], PLD, wmma::mem_row_major);
            wmma::store_matrix_sync(projE + po, accE[tm][tn], PLD, wmma::mem_row_major);
        }
    __syncthreads();

    const int erow    = tid & 63;
    const int quarter = tid >> 6;
    const int cc      = quarter * 32;

    const int gedge = r0 + erow;
    const int sn = sidx[erow];
    const int dn = sidx[BM + erow];

    float vv[32];
    float s0 = 0.f, s1 = 0.f;
    float* oe = out_e + (size_t)gedge * CD + cc;
#pragma unroll
    for (int q = 0; q < 8; ++q) {
        float4 rv  = *reinterpret_cast<const float4*>(projR + erow * PLD + cc + q * 4);
        float4 rbv = *reinterpret_cast<const float4*>(Rb + cc + q * 4);
        float4 ev  = *reinterpret_cast<const float4*>(projE + erow * PLD + cc + q * 4);
        float4 ebv = *reinterpret_cast<const float4*>(Eb + cc + q * 4);
        float4 kv  = *reinterpret_cast<const float4*>(g_Kh + (size_t)sn * CD + cc + q * 4);
        float4 qv  = *reinterpret_cast<const float4*>(g_Qh + (size_t)dn * CD + cc + q * 4);
        float4 v4  = *reinterpret_cast<const float4*>(g_Vh + (size_t)sn * CD + cc + q * 4);
        vv[q*4+0]=v4.x; vv[q*4+1]=v4.y; vv[q*4+2]=v4.z; vv[q*4+3]=v4.w;
        const float pr[4] = {rv.x + rbv.x, rv.y + rbv.y, rv.z + rbv.z, rv.w + rbv.w};
        const float pe[4] = {ev.x + ebv.x, ev.y + ebv.y, ev.z + ebv.z, ev.w + ebv.w};
        const float kk[4] = {kv.x, kv.y, kv.z, kv.w};
        const float qq[4] = {qv.x, qv.y, qv.z, qv.w};
        float sc[4];
#pragma unroll
        for (int j = 0; j < 4; ++j) {
            float t = fmaf(kk[j] * qq[j], 0.25f, pr[j]) * pe[j];
            sc[j] = t;
            if (q < 4) s0 += t; else s1 += t;
        }
        __stcs(reinterpret_cast<float4*>(oe + q * 4), make_float4(sc[0], sc[1], sc[2], sc[3]));
    }

    s0 = __expf(fminf(fmaxf(s0, -5.0f), 5.0f));
    s1 = __expf(fminf(fmaxf(s1, -5.0f), 5.0f));

    float* w = out_h + (size_t)dn * CD + cc;
#pragma unroll
    for (int q = 0; q < 8; ++q) {
        float s = (q < 4) ? s0 : s1;
        red_add_v4(w + q * 4, vv[q*4+0]*s, vv[q*4+1]*s, vv[q*4+2]*s, vv[q*4+3]*s);
    }
    const int hbase = quarter * 2;
    atomicAdd(&g_z[(size_t)dn * NH + hbase],     s0);
    atomicAdd(&g_z[(size_t)dn * NH + hbase + 1], s1);
}

// ================= node kernel: bf16 3-split (unchanged from R9) =================
#define NSM_AH   0
#define NSM_AL   (NSM_AH + 64 * AFULL * 2)
#define NSM_BH   (NSM_AL + 64 * AFULL * 2)
#define NSM_BL   (NSM_BH + KDIM * BLD * 2)
#define NSM_TOTAL (NSM_BL + KDIM * BLD * 2)   // 104448

__global__ __launch_bounds__(256, 2) void node_proj_qkv_kernel(
    const float* __restrict__ h,
    const float* __restrict__ Qb, const float* __restrict__ Kb, const float* __restrict__ Vb,
    float* __restrict__ outQ, float* __restrict__ outK, float* __restrict__ outV)
{
    extern __shared__ char smem[];
    __nv_bfloat16* sAH = reinterpret_cast<__nv_bfloat16*>(smem + NSM_AH);
    __nv_bfloat16* sAL = reinterpret_cast<__nv_bfloat16*>(smem + NSM_AL);
    __nv_bfloat16* sBH = reinterpret_cast<__nv_bfloat16*>(smem + NSM_BH);
    __nv_bfloat16* sBL = reinterpret_cast<__nv_bfloat16*>(smem + NSM_BL);
    float*        proj = reinterpret_cast<float*>(smem + NSM_BH);   // alias B region

    const int tid = threadIdx.x;
    const int wid = tid >> 5;
    const int r0  = blockIdx.x * 64;

    for (int i = tid; i < 64 * 32; i += 256) {
        int row = i >> 5, kq = i & 31;
        float4 v = make_float4(0.f, 0.f, 0.f, 0.f);
        if (r0 + row < NN)
            v = reinterpret_cast<const float4*>(h + (size_t)(r0 + row) * KDIM)[kq];
        const float a[4] = {v.x, v.y, v.z, v.w};
        int off = row * AFULL + kq * 4;
#pragma unroll
        for (int j = 0; j < 4; ++j) {
            __nv_bfloat16 hh, ll;
            cvt_split_bf(a[j], hh, ll);
            sAH[off + j] = hh; sAL[off + j] = ll;
        }
    }

    const float* Bs[3] = {Qb, Kb, Vb};
    float* Os[3] = {outQ, outK, outV};

    const int warp_m = wid & 1;
    const int warp_n = wid >> 1;

    for (int m = 0; m < 3; ++m) {
        __syncthreads();
        for (int i = tid; i < KDIM * (CD / 8); i += 256) {
            int krow = i >> 4, q = i & 15;
            size_t goff = (size_t)krow * CD + q * 8;
            int soff = krow * BLD + q * 8;
            *reinterpret_cast<uint4*>(sBH + soff) = *reinterpret_cast<const uint4*>(&g_Wn_h[m][goff]);
            *reinterpret_cast<uint4*>(sBL + soff) = *reinterpret_cast<const uint4*>(&g_Wn_l[m][goff]);
        }
        __syncthreads();

        wmma::fragment<wmma::accumulator, 16, 16, 16, float> acc[2][2];
#pragma unroll
        for (int tm = 0; tm < 2; ++tm)
#pragma unroll
            for (int tn = 0; tn < 2; ++tn) wmma::fill_fragment(acc[tm][tn], 0.0f);

#pragma unroll
        for (int ks = 0; ks < KDIM / 16; ++ks) {
            wmma::fragment<wmma::matrix_a, 16, 16, 16, __nv_bfloat16, wmma::row_major> aH[2], aL[2];
            wmma::fragment<wmma::matrix_b, 16, 16, 16, __nv_bfloat16, wmma::row_major> bH[2], bL[2];
#pragma unroll
            for (int tm = 0; tm < 2; ++tm) {
                const int ar = warp_m * 32 + tm * 16;
                wmma::load_matrix_sync(aH[tm], sAH + ar * AFULL + ks * 16, AFULL);
                wmma::load_matrix_sync(aL[tm], sAL + ar * AFULL + ks * 16, AFULL);
            }
#pragma unroll
            for (int tn = 0; tn < 2; ++tn) {
                const int bc = warp_n * 32 + tn * 16;
                wmma::load_matrix_sync(bH[tn], sBH + ks * 16 * BLD + bc, BLD);
                wmma::load_matrix_sync(bL[tn], sBL + ks * 16 * BLD + bc, BLD);
            }
#pragma unroll
            for (int tm = 0; tm < 2; ++tm)
#pragma unroll
                for (int tn = 0; tn < 2; ++tn) {
                    wmma::mma_sync(acc[tm][tn], aH[tm], bH[tn], acc[tm][tn]);
                    wmma::mma_sync(acc[tm][tn], aH[tm], bL[tn], acc[tm][tn]);
                    wmma::mma_sync(acc[tm][tn], aL[tm], bH[tn], acc[tm][tn]);
                }
        }

        __syncthreads();
#pragma unroll
        for (int tm = 0; tm < 2; ++tm)
#pragma unroll
            for (int tn = 0; tn < 2; ++tn)
                wmma::store_matrix_sync(proj + (warp_m * 32 + tm * 16) * PLD + warp_n * 32 + tn * 16,
                                        acc[tm][tn], PLD, wmma::mem_row_major);
        __syncthreads();

        const int row = tid >> 2;
        const int cq  = (tid & 3) * 32;
        if (r0 + row < NN) {
            float* out = Os[m] + (size_t)(r0 + row) * CD + cq;
#pragma unroll
            for (int q = 0; q < 8; ++q) {
                float4 v  = *reinterpret_cast<const float4*>(proj + row * PLD + cq + q * 4);
                float4 bv = *reinterpret_cast<const float4*>(Bs[m] + cq + q * 4);
                reinterpret_cast<float4*>(out + q * 4)[0] =
                    make_float4(v.x + bv.x, v.y + bv.y, v.z + bv.z, v.w + bv.w);
            }
        }
    }
}

// ---------------- finalize ----------------
__global__ __launch_bounds__(256) void finalize_kernel(float* __restrict__ out_h)
{
    int i = blockIdx.x * 256 + threadIdx.x;
    const int total = NN * CD / 4;
    if (i >= total) return;
    int n  = i >> 5;
    int cg = i & 31;
    int head = cg >> 2;
    float z = g_z[(size_t)n * NH + head] + 1e-6f;
    float inv = 1.0f / z;
    float4 v = reinterpret_cast<float4*>(out_h)[i];
    v.x *= inv; v.y *= inv; v.z *= inv; v.w *= inv;
    reinterpret_cast<float4*>(out_h)[i] = v;
}

// ---------------- launch ----------------
extern "C" void kernel_launch(void* const* d_in, const int* in_sizes, int n_in,
                              void* d_out, int out_size)
{
    const float* h   = (const float*)d_in[0];
    const float* e   = (const float*)d_in[1];
    const float* kr  = (const float*)d_in[2];
    const int*   src = (const int*)  d_in[3];
    const int*   dst = (const int*)  d_in[4];
    const float* Qw  = (const float*)d_in[5];
    const float* Qb  = (const float*)d_in[6];
    const float* Kw  = (const float*)d_in[7];
    const float* Kb  = (const float*)d_in[8];
    const float* Vw  = (const float*)d_in[9];
    const float* Vb  = (const float*)d_in[10];
    const float* Ew  = (const float*)d_in[11];
    const float* Eb  = (const float*)d_in[12];
    const float* Rw  = (const float*)d_in[13];
    const float* Rb  = (const float*)d_in[14];

    float* out_h = (float*)d_out;
    float* out_e = (float*)d_out + (size_t)NN * CD;

    cudaFuncSetAttribute(node_proj_qkv_kernel, cudaFuncAttributeMaxDynamicSharedMemorySize, NSM_TOTAL);
    cudaFuncSetAttribute(edge_kernel,          cudaFuncAttributeMaxDynamicSharedMemorySize, ESM_TOTAL);

    cudaMemsetAsync(out_h, 0, (size_t)NN * CD * sizeof(float));
    void* zp = nullptr;
    cudaGetSymbolAddress(&zp, g_z);
    cudaMemsetAsync(zp, 0, (size_t)NN * NH * sizeof(float));

    void *qp, *kp, *vp;
    cudaGetSymbolAddress(&qp, g_Qh);
    cudaGetSymbolAddress(&kp, g_Kh);
    cudaGetSymbolAddress(&vp, g_Vh);

    convert_weights_kernel<<<(KDIM * CD + 255) / 256, 256>>>(Ew, Rw, Qw, Kw, Vw);

    const int nodeBlocks = (NN + 63) / 64;  // 782
    node_proj_qkv_kernel<<<nodeBlocks, 256, NSM_TOTAL>>>(
        h, Qb, Kb, Vb, (float*)qp, (float*)kp, (float*)vp);

    edge_kernel<<<EE / BM, 256, ESM_TOTAL>>>(e, kr, src, dst, Eb, Rb, out_h, out_e);

    const int finBlocks = (NN * CD / 4 + 255) / 256;
    finalize_kernel<<<finBlocks, 256>>>(out_h);
}

// round 11
// speedup vs baseline: 3.5412x; 1.0776x over previous
#include <cuda_runtime.h>
#include <cuda_bf16.h>
#include <cuda_fp16.h>
#include <mma.h>
#include <math.h>
#include <stdint.h>

using namespace nvcuda;

#define NN 50000
#define EE 800000
#define KDIM 128
#define CD 128
#define NH 8

#define BM 64        // edges per block (edge kernel)
#define CHK 32       // K chunk
#define KCH (KDIM / CHK)
#define ALD 40       // A smem leading dim (half)
#define AFULL 136    // A smem leading dim full-K (bf16, node)
#define BLD 136      // B smem leading dim (16-bit elems)
#define PLD 132      // proj smem leading dim (floats)

// ---------------- device scratch ----------------
__device__ float g_Qh[(size_t)NN * CD];
__device__ float g_Kh[(size_t)NN * CD];
__device__ float g_Vh[(size_t)NN * CD];
__device__ float g_z[(size_t)NN * NH];
// edge weights: single fp16 (0=Ew 1=Rw)
__device__ __align__(16) __half g_We[2][KDIM * CD];
// node weights: bf16 hi/lo (0=Qw 1=Kw 2=Vw)
__device__ __align__(16) __nv_bfloat16 g_Wn_h[3][KDIM * CD];
__device__ __align__(16) __nv_bfloat16 g_Wn_l[3][KDIM * CD];

__device__ __forceinline__ void red_add_v4(float* p, float a, float b, float c, float d) {
    asm volatile("red.global.add.v4.f32 [%0], {%1, %2, %3, %4};"
                 :: "l"(p), "f"(a), "f"(b), "f"(c), "f"(d) : "memory");
}
__device__ __forceinline__ void cvt_split_bf(float x, __nv_bfloat16& hi, __nv_bfloat16& lo) {
    hi = __float2bfloat16(x);
    lo = __float2bfloat16(x - __bfloat162float(hi));
}
__device__ __forceinline__ void cp16(uint32_t saddr, const void* gptr) {
    asm volatile("cp.async.cg.shared.global [%0], [%1], 16;"
                 :: "r"(saddr), "l"(gptr) : "memory");
}
__device__ __forceinline__ void cp_commit() {
    asm volatile("cp.async.commit_group;" ::: "memory");
}
__device__ __forceinline__ void cp_wait_all() {
    asm volatile("cp.async.wait_group 0;" ::: "memory");
}

// ---------------- weight conversion (once per launch) ----------------
__global__ __launch_bounds__(256) void convert_weights_kernel(
    const float* __restrict__ Ew, const float* __restrict__ Rw,
    const float* __restrict__ Qw, const float* __restrict__ Kw,
    const float* __restrict__ Vw)
{
    int i = blockIdx.x * 256 + threadIdx.x;
    if (i >= KDIM * CD) return;
    g_We[0][i] = __float2half_rn(Ew[i]);
    g_We[1][i] = __float2half_rn(Rw[i]);
    {
        __nv_bfloat16 h, l;
        cvt_split_bf(Qw[i], h, l); g_Wn_h[0][i] = h; g_Wn_l[0][i] = l;
        cvt_split_bf(Kw[i], h, l); g_Wn_h[1][i] = h; g_Wn_l[1][i] = l;
        cvt_split_bf(Vw[i], h, l); g_Wn_h[2][i] = h; g_Wn_l[2][i] = l;
    }
}

// ================= edge kernel: double-buffered pipeline, fp16 A1xB1 =================
#define ESM_SIDX  0                           // 512
#define ESM_A     512
#define ABUF_SZ   (2 * BM * ALD * 2)          // 10240 bytes per buffer (AE + AK)
#define ESM_B     (ESM_A + 2 * ABUF_SZ)       // 20992
#define SBT       (CHK * BLD * 2)             // 8704 bytes per weight sub-tile
#define BBUF_SZ   (2 * SBT)                   // 17408 (BE, BR)
#define ESM_PROJE (ESM_B + 2 * BBUF_SZ)       // 55808
#define ESM_TOTAL (ESM_PROJE + BM * PLD * 4)  // 89600
// projR aliases the full B region (34816 >= 33792), dead after last MMA

__global__ __launch_bounds__(256, 2) void edge_kernel(
    const float* __restrict__ e,
    const float* __restrict__ kr,
    const int*  __restrict__ src,
    const int*  __restrict__ dst,
    const float* __restrict__ Eb,
    const float* __restrict__ Rb,
    float* __restrict__ out_h,
    float* __restrict__ out_e)
{
    extern __shared__ char smem[];
    int*   sidx  = reinterpret_cast<int*>(smem + ESM_SIDX);
    float* projR = reinterpret_cast<float*>(smem + ESM_B);       // alias B bufs
    float* projE = reinterpret_cast<float*>(smem + ESM_PROJE);

    const int tid = threadIdx.x;
    const int wid = tid >> 5;
    const int r0  = blockIdx.x * BM;

    // B-copy mapping: 2 iterations of (krow, q)
    const int bkrow0 = tid >> 4;          // 0..15
    const int bq     = tid & 15;          // uint4 col group

    // ---- issue B(0) cp.async immediately ----
    {
        uint32_t bdst = (uint32_t)__cvta_generic_to_shared(smem + ESM_B);
#pragma unroll
        for (int it = 0; it < 2; ++it) {
            int krow = bkrow0 + 16 * it;
            size_t goff = (size_t)krow * CD + bq * 8;
            uint32_t soff = (uint32_t)(krow * BLD + bq * 8) * 2;
            cp16(bdst + 0 * SBT + soff, &g_We[0][goff]);
            cp16(bdst + 1 * SBT + soff, &g_We[1][goff]);
        }
        cp_commit();
    }

    if (tid < BM) {
        sidx[tid]      = src[r0 + tid];
        sidx[BM + tid] = dst[r0 + tid];
    }

    const int warp_m = wid & 1;    // 2 x 32 edges
    const int warp_n = wid >> 1;   // 4 x 32 cols

    const int arow0 = tid >> 3;    // 0..31
    const int aq    = tid & 7;     // float4 index in k-chunk

    wmma::fragment<wmma::accumulator, 16, 16, 16, float> accE[2][2], accR[2][2];
#pragma unroll
    for (int tm = 0; tm < 2; ++tm)
#pragma unroll
        for (int tn = 0; tn < 2; ++tn) {
            wmma::fill_fragment(accE[tm][tn], 0.0f);
            wmma::fill_fragment(accR[tm][tn], 0.0f);
        }

    // prologue: prefetch chunk 0 e/kr to registers
    float4 pve[2], pvk[2];
#pragma unroll
    for (int it = 0; it < 2; ++it) {
        const int row = arow0 + 32 * it;
        pve[it] = *reinterpret_cast<const float4*>(e  + (size_t)(r0 + row) * KDIM + aq * 4);
        pvk[it] = *reinterpret_cast<const float4*>(kr + (size_t)(r0 + row) * KDIM + aq * 4);
    }

    for (int ch = 0; ch < KCH; ++ch) {
        const int ab = ch & 1;
        __half* sAE = reinterpret_cast<__half*>(smem + ESM_A + ab * ABUF_SZ);
        __half* sAK = sAE + BM * ALD;

        // ---- STS A(ch) from prefetched regs (fp16 single) ----
#pragma unroll
        for (int it = 0; it < 2; ++it) {
            const int row = arow0 + 32 * it;
            const int off = row * ALD + aq * 4;
            __half2* pe2 = reinterpret_cast<__half2*>(sAE + off);
            __half2* pk2 = reinterpret_cast<__half2*>(sAK + off);
            pe2[0] = __halves2half2(__float2half_rn(pve[it].x), __float2half_rn(pve[it].y));
            pe2[1] = __halves2half2(__float2half_rn(pve[it].z), __float2half_rn(pve[it].w));
            pk2[0] = __halves2half2(__float2half_rn(pvk[it].x), __float2half_rn(pvk[it].y));
            pk2[1] = __halves2half2(__float2half_rn(pvk[it].z), __float2half_rn(pvk[it].w));
        }
        // ---- prefetch A(ch+1) regs ----
        if (ch < KCH - 1) {
            const int gk = (ch + 1) * CHK + aq * 4;
#pragma unroll
            for (int it = 0; it < 2; ++it) {
                const int row = arow0 + 32 * it;
                pve[it] = *reinterpret_cast<const float4*>(e  + (size_t)(r0 + row) * KDIM + gk);
                pvk[it] = *reinterpret_cast<const float4*>(kr + (size_t)(r0 + row) * KDIM + gk);
            }
        }

        // ---- B(ch) complete + A STS visible ----
        cp_wait_all();
        __syncthreads();

        // ---- issue B(ch+1), overlaps this chunk's MMAs ----
        if (ch < KCH - 1) {
            uint32_t bdst = (uint32_t)__cvta_generic_to_shared(
                smem + ESM_B + ((ch + 1) & 1) * BBUF_SZ);
#pragma unroll
            for (int it = 0; it < 2; ++it) {
                int krow = bkrow0 + 16 * it;
                size_t goff = (size_t)((ch + 1) * CHK + krow) * CD + bq * 8;
                uint32_t soff = (uint32_t)(krow * BLD + bq * 8) * 2;
                cp16(bdst + 0 * SBT + soff, &g_We[0][goff]);
                cp16(bdst + 1 * SBT + soff, &g_We[1][goff]);
            }
            cp_commit();
        }

        __half* sB  = reinterpret_cast<__half*>(smem + ESM_B + ab * BBUF_SZ);
        __half* sBE = sB;
        __half* sBR = sB + SBT / 2;

        // ---- MMAs (single-B) ----
#pragma unroll
        for (int ks = 0; ks < 2; ++ks) {
            wmma::fragment<wmma::matrix_a, 16, 16, 16, __half, wmma::row_major> a[2];
            wmma::fragment<wmma::matrix_b, 16, 16, 16, __half, wmma::row_major> b[2];
            // E
#pragma unroll
            for (int tm = 0; tm < 2; ++tm)
                wmma::load_matrix_sync(a[tm], sAE + (warp_m * 32 + tm * 16) * ALD + ks * 16, ALD);
#pragma unroll
            for (int tn = 0; tn < 2; ++tn)
                wmma::load_matrix_sync(b[tn], sBE + ks * 16 * BLD + warp_n * 32 + tn * 16, BLD);
#pragma unroll
            for (int tm = 0; tm < 2; ++tm)
#pragma unroll
                for (int tn = 0; tn < 2; ++tn)
                    wmma::mma_sync(accE[tm][tn], a[tm], b[tn], accE[tm][tn]);
            // R
#pragma unroll
            for (int tm = 0; tm < 2; ++tm)
                wmma::load_matrix_sync(a[tm], sAK + (warp_m * 32 + tm * 16) * ALD + ks * 16, ALD);
#pragma unroll
            for (int tn = 0; tn < 2; ++tn)
                wmma::load_matrix_sync(b[tn], sBR + ks * 16 * BLD + warp_n * 32 + tn * 16, BLD);
#pragma unroll
            for (int tm = 0; tm < 2; ++tm)
#pragma unroll
                for (int tn = 0; tn < 2; ++tn)
                    wmma::mma_sync(accR[tm][tn], a[tm], b[tn], accR[tm][tn]);
        }
    }

    // ---- epilogue: stage both projections (projR aliases dead B bufs) ----
    __syncthreads();
#pragma unroll
    for (int tm = 0; tm < 2; ++tm)
#pragma unroll
        for (int tn = 0; tn < 2; ++tn) {
            const int po = (warp_m * 32 + tm * 16) * PLD + warp_n * 32 + tn * 16;
            wmma::store_matrix_sync(projR + po, accR[tm][tn], PLD, wmma::mem_row_major);
            wmma::store_matrix_sync(projE + po, accE[tm][tn], PLD, wmma::mem_row_major);
        }
    __syncthreads();

    const int erow    = tid & 63;
    const int quarter = tid >> 6;
    const int cc      = quarter * 32;

    const int gedge = r0 + erow;
    const int sn = sidx[erow];
    const int dn = sidx[BM + erow];

    float vv[32];
    float s0 = 0.f, s1 = 0.f;
    float* oe = out_e + (size_t)gedge * CD + cc;
#pragma unroll
    for (int q = 0; q < 8; ++q) {
        float4 rv  = *reinterpret_cast<const float4*>(projR + erow * PLD + cc + q * 4);
        float4 rbv = *reinterpret_cast<const float4*>(Rb + cc + q * 4);
        float4 ev  = *reinterpret_cast<const float4*>(projE + erow * PLD + cc + q * 4);
        float4 ebv = *reinterpret_cast<const float4*>(Eb + cc + q * 4);
        float4 kv  = *reinterpret_cast<const float4*>(g_Kh + (size_t)sn * CD + cc + q * 4);
        float4 qv  = *reinterpret_cast<const float4*>(g_Qh + (size_t)dn * CD + cc + q * 4);
        float4 v4  = *reinterpret_cast<const float4*>(g_Vh + (size_t)sn * CD + cc + q * 4);
        vv[q*4+0]=v4.x; vv[q*4+1]=v4.y; vv[q*4+2]=v4.z; vv[q*4+3]=v4.w;
        const float pr[4] = {rv.x + rbv.x, rv.y + rbv.y, rv.z + rbv.z, rv.w + rbv.w};
        const float pe[4] = {ev.x + ebv.x, ev.y + ebv.y, ev.z + ebv.z, ev.w + ebv.w};
        const float kk[4] = {kv.x, kv.y, kv.z, kv.w};
        const float qq[4] = {qv.x, qv.y, qv.z, qv.w};
        float sc[4];
#pragma unroll
        for (int j = 0; j < 4; ++j) {
            float t = fmaf(kk[j] * qq[j], 0.25f, pr[j]) * pe[j];
            sc[j] = t;
            if (q < 4) s0 += t; else s1 += t;
        }
        __stcs(reinterpret_cast<float4*>(oe + q * 4), make_float4(sc[0], sc[1], sc[2], sc[3]));
    }

    s0 = __expf(fminf(fmaxf(s0, -5.0f), 5.0f));
    s1 = __expf(fminf(fmaxf(s1, -5.0f), 5.0f));

    float* w = out_h + (size_t)dn * CD + cc;
#pragma unroll
    for (int q = 0; q < 8; ++q) {
        float s = (q < 4) ? s0 : s1;
        red_add_v4(w + q * 4, vv[q*4+0]*s, vv[q*4+1]*s, vv[q*4+2]*s, vv[q*4+3]*s);
    }
    const int hbase = quarter * 2;
    atomicAdd(&g_z[(size_t)dn * NH + hbase],     s0);
    atomicAdd(&g_z[(size_t)dn * NH + hbase + 1], s1);
}

// ================= node kernel: bf16 3-split (unchanged) =================
#define NSM_AH   0
#define NSM_AL   (NSM_AH + 64 * AFULL * 2)
#define NSM_BH   (NSM_AL + 64 * AFULL * 2)
#define NSM_BL   (NSM_BH + KDIM * BLD * 2)
#define NSM_TOTAL (NSM_BL + KDIM * BLD * 2)   // 104448

__global__ __launch_bounds__(256, 2) void node_proj_qkv_kernel(
    const float* __restrict__ h,
    const float* __restrict__ Qb, const float* __restrict__ Kb, const float* __restrict__ Vb,
    float* __restrict__ outQ, float* __restrict__ outK, float* __restrict__ outV)
{
    extern __shared__ char smem[];
    __nv_bfloat16* sAH = reinterpret_cast<__nv_bfloat16*>(smem + NSM_AH);
    __nv_bfloat16* sAL = reinterpret_cast<__nv_bfloat16*>(smem + NSM_AL);
    __nv_bfloat16* sBH = reinterpret_cast<__nv_bfloat16*>(smem + NSM_BH);
    __nv_bfloat16* sBL = reinterpret_cast<__nv_bfloat16*>(smem + NSM_BL);
    float*        proj = reinterpret_cast<float*>(smem + NSM_BH);   // alias B region

    const int tid = threadIdx.x;
    const int wid = tid >> 5;
    const int r0  = blockIdx.x * 64;

    for (int i = tid; i < 64 * 32; i += 256) {
        int row = i >> 5, kq = i & 31;
        float4 v = make_float4(0.f, 0.f, 0.f, 0.f);
        if (r0 + row < NN)
            v = reinterpret_cast<const float4*>(h + (size_t)(r0 + row) * KDIM)[kq];
        const float a[4] = {v.x, v.y, v.z, v.w};
        int off = row * AFULL + kq * 4;
#pragma unroll
        for (int j = 0; j < 4; ++j) {
            __nv_bfloat16 hh, ll;
            cvt_split_bf(a[j], hh, ll);
            sAH[off + j] = hh; sAL[off + j] = ll;
        }
    }

    const float* Bs[3] = {Qb, Kb, Vb};
    float* Os[3] = {outQ, outK, outV};

    const int warp_m = wid & 1;
    const int warp_n = wid >> 1;

    for (int m = 0; m < 3; ++m) {
        __syncthreads();
        for (int i = tid; i < KDIM * (CD / 8); i += 256) {
            int krow = i >> 4, q = i & 15;
            size_t goff = (size_t)krow * CD + q * 8;
            int soff = krow * BLD + q * 8;
            *reinterpret_cast<uint4*>(sBH + soff) = *reinterpret_cast<const uint4*>(&g_Wn_h[m][goff]);
            *reinterpret_cast<uint4*>(sBL + soff) = *reinterpret_cast<const uint4*>(&g_Wn_l[m][goff]);
        }
        __syncthreads();

        wmma::fragment<wmma::accumulator, 16, 16, 16, float> acc[2][2];
#pragma unroll
        for (int tm = 0; tm < 2; ++tm)
#pragma unroll
            for (int tn = 0; tn < 2; ++tn) wmma::fill_fragment(acc[tm][tn], 0.0f);

#pragma unroll
        for (int ks = 0; ks < KDIM / 16; ++ks) {
            wmma::fragment<wmma::matrix_a, 16, 16, 16, __nv_bfloat16, wmma::row_major> aH[2], aL[2];
            wmma::fragment<wmma::matrix_b, 16, 16, 16, __nv_bfloat16, wmma::row_major> bH[2], bL[2];
#pragma unroll
            for (int tm = 0; tm < 2; ++tm) {
                const int ar = warp_m * 32 + tm * 16;
                wmma::load_matrix_sync(aH[tm], sAH + ar * AFULL + ks * 16, AFULL);
                wmma::load_matrix_sync(aL[tm], sAL + ar * AFULL + ks * 16, AFULL);
            }
#pragma unroll
            for (int tn = 0; tn < 2; ++tn) {
                const int bc = warp_n * 32 + tn * 16;
                wmma::load_matrix_sync(bH[tn], sBH + ks * 16 * BLD + bc, BLD);
                wmma::load_matrix_sync(bL[tn], sBL + ks * 16 * BLD + bc, BLD);
            }
#pragma unroll
            for (int tm = 0; tm < 2; ++tm)
#pragma unroll
                for (int tn = 0; tn < 2; ++tn) {
                    wmma::mma_sync(acc[tm][tn], aH[tm], bH[tn], acc[tm][tn]);
                    wmma::mma_sync(acc[tm][tn], aH[tm], bL[tn], acc[tm][tn]);
                    wmma::mma_sync(acc[tm][tn], aL[tm], bH[tn], acc[tm][tn]);
                }
        }

        __syncthreads();
#pragma unroll
        for (int tm = 0; tm < 2; ++tm)
#pragma unroll
            for (int tn = 0; tn < 2; ++tn)
                wmma::store_matrix_sync(proj + (warp_m * 32 + tm * 16) * PLD + warp_n * 32 + tn * 16,
                                        acc[tm][tn], PLD, wmma::mem_row_major);
        __syncthreads();

        const int row = tid >> 2;
        const int cq  = (tid & 3) * 32;
        if (r0 + row < NN) {
            float* out = Os[m] + (size_t)(r0 + row) * CD + cq;
#pragma unroll
            for (int q = 0; q < 8; ++q) {
                float4 v  = *reinterpret_cast<const float4*>(proj + row * PLD + cq + q * 4);
                float4 bv = *reinterpret_cast<const float4*>(Bs[m] + cq + q * 4);
                reinterpret_cast<float4*>(out + q * 4)[0] =
                    make_float4(v.x + bv.x, v.y + bv.y, v.z + bv.z, v.w + bv.w);
            }
        }
    }
}

// ---------------- finalize ----------------
__global__ __launch_bounds__(256) void finalize_kernel(float* __restrict__ out_h)
{
    int i = blockIdx.x * 256 + threadIdx.x;
    const int total = NN * CD / 4;
    if (i >= total) return;
    int n  = i >> 5;
    int cg = i & 31;
    int head = cg >> 2;
    float z = g_z[(size_t)n * NH + head] + 1e-6f;
    float inv = 1.0f / z;
    float4 v = reinterpret_cast<float4*>(out_h)[i];
    v.x *= inv; v.y *= inv; v.z *= inv; v.w *= inv;
    reinterpret_cast<float4*>(out_h)[i] = v;
}

// ---------------- launch ----------------
extern "C" void kernel_launch(void* const* d_in, const int* in_sizes, int n_in,
                              void* d_out, int out_size)
{
    const float* h   = (const float*)d_in[0];
    const float* e   = (const float*)d_in[1];
    const float* kr  = (const float*)d_in[2];
    const int*   src = (const int*)  d_in[3];
    const int*   dst = (const int*)  d_in[4];
    const float* Qw  = (const float*)d_in[5];
    const float* Qb  = (const float*)d_in[6];
    const float* Kw  = (const float*)d_in[7];
    const float* Kb  = (const float*)d_in[8];
    const float* Vw  = (const float*)d_in[9];
    const float* Vb  = (const float*)d_in[10];
    const float* Ew  = (const float*)d_in[11];
    const float* Eb  = (const float*)d_in[12];
    const float* Rw  = (const float*)d_in[13];
    const float* Rb  = (const float*)d_in[14];

    float* out_h = (float*)d_out;
    float* out_e = (float*)d_out + (size_t)NN * CD;

    cudaFuncSetAttribute(node_proj_qkv_kernel, cudaFuncAttributeMaxDynamicSharedMemorySize, NSM_TOTAL);
    cudaFuncSetAttribute(edge_kernel,          cudaFuncAttributeMaxDynamicSharedMemorySize, ESM_TOTAL);

    cudaMemsetAsync(out_h, 0, (size_t)NN * CD * sizeof(float));
    void* zp = nullptr;
    cudaGetSymbolAddress(&zp, g_z);
    cudaMemsetAsync(zp, 0, (size_t)NN * NH * sizeof(float));

    void *qp, *kp, *vp;
    cudaGetSymbolAddress(&qp, g_Qh);
    cudaGetSymbolAddress(&kp, g_Kh);
    cudaGetSymbolAddress(&vp, g_Vh);

    convert_weights_kernel<<<(KDIM * CD + 255) / 256, 256>>>(Ew, Rw, Qw, Kw, Vw);

    const int nodeBlocks = (NN + 63) / 64;  // 782
    node_proj_qkv_kernel<<<nodeBlocks, 256, NSM_TOTAL>>>(
        h, Qb, Kb, Vb, (float*)qp, (float*)kp, (float*)vp);

    edge_kernel<<<EE / BM, 256, ESM_TOTAL>>>(e, kr, src, dst, Eb, Rb, out_h, out_e);

    const int finBlocks = (NN * CD / 4 + 255) / 256;
    finalize_kernel<<<finBlocks, 256>>>(out_h);
}